// round 6
// baseline (speedup 1.0000x reference)
#include <cuda_runtime.h>
#include <math.h>

#define B_TOTAL 131072
#define KNB 5
#define TILE_B 32
#define ROWSF (TILE_B * KNB)   // 160
#define COMB 128
#define HID 256
#define AH 128
#define CLD 132                // comb/Ws leading dim (4g+t bank walk)
#define W2LD 36                // W2 chunk leading dim (4g+t bank walk)

typedef unsigned int uint32;

// ---------------- device globals ----------------
__device__ uint32 g_w1aT[AH * COMB];        // attn_W1^T  [n=128][k=128] tf32
__device__ uint32 g_w1vT[HID * COMB];       // val_W1^T   [n=256][k=128] tf32
__device__ uint32 g_w2T[HID * HID];         // val_W2^T   [n=256][k=256] tf32
__device__ int g_flag_u8, g_flag_f32;

// ---------------- helpers ----------------
__device__ __forceinline__ uint32 f2tf(float f) {
    uint32 r; asm("cvt.rna.tf32.f32 %0, %1;" : "=r"(r) : "f"(f)); return r;
}
__device__ __forceinline__ void mma_tf32(float d[4], const uint32 a[4], const uint32 b[2]) {
    asm("mma.sync.aligned.m16n8k8.row.col.f32.tf32.tf32.f32 "
        "{%0,%1,%2,%3}, {%4,%5,%6,%7}, {%8,%9}, {%0,%1,%2,%3};"
        : "+f"(d[0]), "+f"(d[1]), "+f"(d[2]), "+f"(d[3])
        : "r"(a[0]), "r"(a[1]), "r"(a[2]), "r"(a[3]), "r"(b[0]), "r"(b[1]));
}
__device__ __forceinline__ float gelu_exact(float x) {
    return 0.5f * x * (1.0f + erff(x * 0.70710678118654752f));
}

// ---------------- prep: convert + transpose weights to tf32 ----------------
__global__ void prep_weights(const float* __restrict__ attn_W1,
                             const float* __restrict__ val_W1,
                             const float* __restrict__ val_W2) {
    int tid = blockIdx.x * blockDim.x + threadIdx.x;
    int stride = gridDim.x * blockDim.x;
    for (int i = tid; i < AH * COMB; i += stride) {
        int n = i >> 7, k = i & 127;
        g_w1aT[i] = f2tf(attn_W1[k * AH + n]);
    }
    for (int i = tid; i < HID * COMB; i += stride) {
        int n = i >> 7, k = i & 127;
        g_w1vT[i] = f2tf(val_W1[k * HID + n]);
    }
    for (int i = tid; i < HID * HID; i += stride) {
        int n = i >> 8, k = i & 255;
        g_w2T[i] = f2tf(val_W2[k * HID + n]);
    }
}

// ---------------- valid-dtype probe ----------------
__global__ void reset_flags() { g_flag_u8 = 0; g_flag_f32 = 0; }

__global__ void detect_valid(const unsigned int* __restrict__ v, int n) {
    int f8 = 0, f32 = 0;
    for (int i = blockIdx.x * blockDim.x + threadIdx.x; i < n; i += gridDim.x * blockDim.x) {
        unsigned int w = v[i];
        if (w == 0x3F800000u) f32 = 1;
        else if (w > 1u) f8 = 1;
    }
    if (__syncthreads_or(f8) && threadIdx.x == 0) atomicOr(&g_flag_u8, 1);
    if (__syncthreads_or(f32) && threadIdx.x == 0) atomicOr(&g_flag_f32, 1);
}

// ---------------- fully fused kernel ----------------
// smem (floats):
// comb  @0     : 21120   (160 x 132, tf32 bits, k-major row perm)
// Wbuf  @21120 : 16896   (GEMM1/2: 128x132 ; out: 256x36=9216)
// hbar  @38016 : 8320    (32 x 260, tf32 bits)
// P     @46336 : 8448    (2 x 32 x 132 partials / 160x9 score partials)
// feat  @54784 : 960 | score @55744: 160 | wgt @55904: 160
// biasA @56064 : 128 | w2a @56192: 128 | biasV @56320: 256
// b2s   @56576 : 256 | fbs @56832: 256 | cWs @57088: 192 | cbs @57280: 32
// ridx  @57312 : 160 | sidx @57472: 160 | anyv @57632: 32
// total 57664 floats = 230656 B
#define SMEM_BYTES 230656

__global__ void __launch_bounds__(512, 1) fused_all(
    const int* __restrict__ res_idx,
    const int* __restrict__ ss_idx,
    const float* __restrict__ dist,
    const int* __restrict__ seq_sep,
    const float* __restrict__ angles,
    const void* __restrict__ validp,
    const float* __restrict__ res_table,
    const float* __restrict__ ss_table,
    const float* __restrict__ cont_W,
    const float* __restrict__ cont_b,
    const float* __restrict__ attn_b1,
    const float* __restrict__ attn_W2,
    const float* __restrict__ attn_b2,
    const float* __restrict__ val_b1,
    const float* __restrict__ val_b2,
    const float* __restrict__ fallback,
    float* __restrict__ out)
{
    extern __shared__ float sm[];
    float* comb    = sm;
    float* Wbuf    = sm + 21120;
    float* hbar_s  = sm + 38016;
    float* P       = sm + 46336;
    float* feat    = sm + 54784;
    float* score_s = sm + 55744;
    float* wgt_s   = sm + 55904;
    float* biasA   = sm + 56064;
    float* w2a_s   = sm + 56192;
    float* biasV   = sm + 56320;
    float* b2s     = sm + 56576;
    float* fbs     = sm + 56832;
    float* cWs     = sm + 57088;
    float* cbs     = sm + 57280;
    int*   ridx    = (int*)(sm + 57312);
    int*   sidx    = (int*)(sm + 57472);
    int*   anyv_s  = (int*)(sm + 57632);

    const int tid  = threadIdx.x;
    const int lane = tid & 31;
    const int warp = tid >> 5;
    const int g    = lane >> 2;     // 0..7
    const int t    = lane & 3;      // 0..3
    const int wm   = warp >> 3;     // 0..1 (M half)
    const int wn   = warp & 7;      // 0..7
    const int nb   = wn * 16;
    const int mrow0 = wm * 80 + g;
    const int b0   = blockIdx.x * TILE_B;
    const int gr0  = b0 * KNB;

    const uint32* combu = (const uint32*)comb;
    const uint32* wsu   = (const uint32*)Wbuf;
    const uint32* hbU   = (const uint32*)hbar_s;

    // ---------- phase 0: constants + features ----------
    for (int i = tid; i < 192; i += 512) cWs[i] = cont_W[i];
    if (tid < 32) cbs[tid] = cont_b[tid];
    if (tid < AH) { biasA[tid] = attn_b1[tid]; w2a_s[tid] = attn_W2[tid]; }
    for (int i = tid; i < HID; i += 512) {
        biasV[i] = val_b1[i];
        b2s[i] = val_b2[i];
        fbs[i] = fallback[i];
    }
    if (tid < ROWSF) {
        int gr = gr0 + tid;
        ridx[tid] = res_idx[gr];
        sidx[tid] = ss_idx[gr];
        float d = dist[gr];
        if (d != d) d = 0.0f;
        feat[tid * 6 + 0] = d * (1.0f / 15.0f);
        feat[tid * 6 + 1] = log1pf(fabsf((float)seq_sep[gr])) * 0.2f;
        float4 a = ((const float4*)angles)[gr];
        feat[tid * 6 + 2] = (a.x != a.x) ? 0.0f : a.x;
        feat[tid * 6 + 3] = (a.y != a.y) ? 0.0f : a.y;
        feat[tid * 6 + 4] = (a.z != a.z) ? 0.0f : a.z;
        feat[tid * 6 + 5] = (a.w != a.w) ? 0.0f : a.w;
    }
    __syncthreads();

    // ---------- phase 1: build comb (k-major perm rt=(j%5)*32+(j/5)) + stage attn_W1T ----------
    for (int i = tid; i < ROWSF * 64; i += 512) {
        int j = i >> 6, c = i & 63;
        int rt = (j % 5) * 32 + (j / 5);
        comb[rt * CLD + c] = __uint_as_float(f2tf(res_table[ridx[j] * 64 + c]));
    }
    for (int i = tid; i < ROWSF * 32; i += 512) {
        int j = i >> 5, c = i & 31;
        int rt = (j % 5) * 32 + (j / 5);
        comb[rt * CLD + 64 + c] = __uint_as_float(f2tf(ss_table[sidx[j] * 32 + c]));
    }
    for (int i = tid; i < ROWSF * 32; i += 512) {
        int j = i >> 5, c = i & 31;
        int rt = (j % 5) * 32 + (j / 5);
        float s = cbs[c];
        #pragma unroll
        for (int jj = 0; jj < 6; jj++) s += feat[j * 6 + jj] * cWs[jj * 32 + c];
        comb[rt * CLD + 96 + c] = __uint_as_float(f2tf(s));
    }
    // attn_W1T: 128 rows x 32 float4
    for (int i = tid; i < AH * 32; i += 512) {
        int n = i >> 5, q = i & 31;
        ((float4*)(Wbuf + n * CLD))[q] = ((const float4*)g_w1aT)[n * 32 + q];
    }
    __syncthreads();

    // ---------- phase 2: GEMM1 (attention scores) ----------
    {
        float acc[5][2][4];
        #pragma unroll
        for (int mi = 0; mi < 5; mi++)
            #pragma unroll
            for (int ni = 0; ni < 2; ni++)
                #pragma unroll
                for (int q = 0; q < 4; q++) acc[mi][ni][q] = 0.0f;

        #pragma unroll 2
        for (int ks = 0; ks < 16; ks++) {
            int kb = ks * 8;
            uint32 a[5][4];
            #pragma unroll
            for (int mi = 0; mi < 5; mi++) {
                const uint32* base = combu + (mrow0 + mi * 16) * CLD + kb + t;
                a[mi][0] = base[0];
                a[mi][1] = base[8 * CLD];
                a[mi][2] = base[4];
                a[mi][3] = base[8 * CLD + 4];
            }
            uint32 bb[2][2];
            #pragma unroll
            for (int ni = 0; ni < 2; ni++) {
                const uint32* bp = wsu + (nb + ni * 8 + g) * CLD + kb + t;
                bb[ni][0] = bp[0];
                bb[ni][1] = bp[4];
            }
            #pragma unroll
            for (int mi = 0; mi < 5; mi++)
                #pragma unroll
                for (int ni = 0; ni < 2; ni++)
                    mma_tf32(acc[mi][ni], a[mi], bb[ni]);
        }
        #pragma unroll
        for (int mi = 0; mi < 5; mi++) {
            #pragma unroll
            for (int rh = 0; rh < 2; rh++) {
                int row = mrow0 + mi * 16 + 8 * rh;
                float p = 0.0f;
                #pragma unroll
                for (int ni = 0; ni < 2; ni++) {
                    #pragma unroll
                    for (int c = 0; c < 2; c++) {
                        int col = nb + ni * 8 + 2 * t + c;
                        p += gelu_exact(acc[mi][ni][rh * 2 + c] + biasA[col]) * w2a_s[col];
                    }
                }
                p += __shfl_xor_sync(0xFFFFFFFFu, p, 1);
                p += __shfl_xor_sync(0xFFFFFFFFu, p, 2);
                if (t == 0) P[row * 9 + wn] = p;
            }
        }
    }
    __syncthreads();
    if (tid < ROWSF) {
        float s = 0.0f;
        #pragma unroll
        for (int w = 0; w < 8; w++) s += P[tid * 9 + w];
        score_s[tid] = s;
    }
    __syncthreads();

    // ---------- phase 3: softmax + stage val_W1T half0 ----------
    if (tid < TILE_B) {
        int gb = b0 + tid;
        float ab2 = attn_b2[0];
        int fu8 = g_flag_u8, ff32 = g_flag_f32;
        float s[KNB];
        int any = 0;
        #pragma unroll
        for (int k = 0; k < KNB; k++) {
            int idx = gb * KNB + k;
            int v;
            if (ff32)      v = (((const float*)validp)[idx] != 0.0f);
            else if (fu8)  v = (((const unsigned char*)validp)[idx] != 0);
            else           v = (((const int*)validp)[idx] != 0);
            any |= v;
            s[k] = v ? (score_s[k * 32 + tid] + ab2) : -10000.0f;
        }
        float m = s[0];
        #pragma unroll
        for (int k = 1; k < KNB; k++) m = fmaxf(m, s[k]);
        float e[KNB], sum = 0.0f;
        #pragma unroll
        for (int k = 0; k < KNB; k++) { e[k] = expf(s[k] - m); sum += e[k]; }
        float inv = 1.0f / sum;
        #pragma unroll
        for (int k = 0; k < KNB; k++) wgt_s[k * 32 + tid] = e[k] * inv;
        anyv_s[tid] = any;
    }
    for (int i = tid; i < 128 * 32; i += 512) {
        int n = i >> 5, q = i & 31;
        ((float4*)(Wbuf + n * CLD))[q] = ((const float4*)g_w1vT)[n * 32 + q];
    }
    __syncthreads();

    // ---------- phases 4-5: GEMM2 halves, register-local weighted reduce ----------
    #pragma unroll 1
    for (int half = 0; half < 2; half++) {
        if (half == 1) {
            for (int i = tid; i < 128 * 32; i += 512) {
                int n = i >> 5, q = i & 31;
                ((float4*)(Wbuf + n * CLD))[q] = ((const float4*)g_w1vT)[(128 + n) * 32 + q];
            }
            __syncthreads();
        }
        float acc[5][2][4];
        #pragma unroll
        for (int mi = 0; mi < 5; mi++)
            #pragma unroll
            for (int ni = 0; ni < 2; ni++)
                #pragma unroll
                for (int q = 0; q < 4; q++) acc[mi][ni][q] = 0.0f;

        #pragma unroll 2
        for (int ks = 0; ks < 16; ks++) {
            int kb = ks * 8;
            uint32 a[5][4];
            #pragma unroll
            for (int mi = 0; mi < 5; mi++) {
                const uint32* base = combu + (mrow0 + mi * 16) * CLD + kb + t;
                a[mi][0] = base[0];
                a[mi][1] = base[8 * CLD];
                a[mi][2] = base[4];
                a[mi][3] = base[8 * CLD + 4];
            }
            uint32 bb[2][2];
            #pragma unroll
            for (int ni = 0; ni < 2; ni++) {
                const uint32* bp = wsu + (nb + ni * 8 + g) * CLD + kb + t;
                bb[ni][0] = bp[0];
                bb[ni][1] = bp[4];
            }
            #pragma unroll
            for (int mi = 0; mi < 5; mi++)
                #pragma unroll
                for (int ni = 0; ni < 2; ni++)
                    mma_tf32(acc[mi][ni], a[mi], bb[ni]);
        }
        float hb[4][4];
        #pragma unroll
        for (int lb = 0; lb < 4; lb++)
            #pragma unroll
            for (int cc = 0; cc < 4; cc++) hb[lb][cc] = 0.0f;
        #pragma unroll
        for (int mi = 0; mi < 5; mi++) {
            #pragma unroll
            for (int rh = 0; rh < 2; rh++) {
                int row = mrow0 + mi * 16 + 8 * rh;
                float wk = wgt_s[row];
                int lb = (row & 31) >> 3;
                #pragma unroll
                for (int ni = 0; ni < 2; ni++) {
                    #pragma unroll
                    for (int c = 0; c < 2; c++) {
                        int col = nb + ni * 8 + 2 * t + c;
                        hb[lb][ni * 2 + c] += wk * gelu_exact(acc[mi][ni][rh * 2 + c] + biasV[half * 128 + col]);
                    }
                }
            }
        }
        __syncthreads();
        #pragma unroll
        for (int lb = 0; lb < 4; lb++) {
            int b = g + 8 * lb;
            #pragma unroll
            for (int ni = 0; ni < 2; ni++)
                #pragma unroll
                for (int c = 0; c < 2; c++)
                    P[wm * 4224 + b * 132 + nb + ni * 8 + 2 * t + c] = hb[lb][ni * 2 + c];
        }
        __syncthreads();
        // combine wm halves -> hbar (store tf32 bits, ready as MMA A operand)
        for (int i = tid; i < TILE_B * 128; i += 512) {
            int b = i >> 7, col = i & 127;
            float v = P[b * 132 + col] + P[4224 + b * 132 + col];
            hbar_s[b * 260 + half * 128 + col] = __uint_as_float(f2tf(v));
        }
    }
    __syncthreads();

    // ---------- phase 6: output GEMM (32 x 256) @ (256 x 256) in-block ----------
    {
        const int nb2 = warp * 16;      // warp's 16 output cols
        float acc[2][2][4];
        #pragma unroll
        for (int mi = 0; mi < 2; mi++)
            #pragma unroll
            for (int ni = 0; ni < 2; ni++)
                #pragma unroll
                for (int q = 0; q < 4; q++) acc[mi][ni][q] = 0.0f;

        #pragma unroll 1
        for (int kc = 0; kc < 8; kc++) {
            // stage W2 chunk [256 n][32 k] (+4 pad)
            for (int i = tid; i < 256 * 8; i += 512) {
                int n = i >> 3, q = i & 7;
                ((float4*)(Wbuf + n * W2LD))[q] = ((const float4*)g_w2T)[n * 64 + kc * 8 + q];
            }
            __syncthreads();
            #pragma unroll
            for (int ks = 0; ks < 4; ks++) {
                int kb = ks * 8;
                int kabs = kc * 32 + kb;
                uint32 a[2][4];
                #pragma unroll
                for (int mi = 0; mi < 2; mi++) {
                    const uint32* base = hbU + (mi * 16 + g) * 260 + kabs + t;
                    a[mi][0] = base[0];
                    a[mi][1] = base[8 * 260];
                    a[mi][2] = base[4];
                    a[mi][3] = base[8 * 260 + 4];
                }
                uint32 bb[2][2];
                #pragma unroll
                for (int ni = 0; ni < 2; ni++) {
                    const uint32* bp = wsu + (nb2 + ni * 8 + g) * W2LD + kb + t;
                    bb[ni][0] = bp[0];
                    bb[ni][1] = bp[4];
                }
                #pragma unroll
                for (int mi = 0; mi < 2; mi++)
                    #pragma unroll
                    for (int ni = 0; ni < 2; ni++)
                        mma_tf32(acc[mi][ni], a[mi], bb[ni]);
            }
            __syncthreads();
        }

        // epilogue: bias or fallback, direct gmem store
        #pragma unroll
        for (int mi = 0; mi < 2; mi++) {
            #pragma unroll
            for (int rh = 0; rh < 2; rh++) {
                int b = mi * 16 + g + 8 * rh;
                int av = anyv_s[b];
                int row = b0 + b;
                #pragma unroll
                for (int ni = 0; ni < 2; ni++) {
                    int colb = nb2 + ni * 8 + 2 * t;
                    float x0 = acc[mi][ni][rh * 2 + 0];
                    float x1 = acc[mi][ni][rh * 2 + 1];
                    float2 o;
                    if (av) { o.x = x0 + b2s[colb]; o.y = x1 + b2s[colb + 1]; }
                    else    { o.x = fbs[colb];      o.y = fbs[colb + 1]; }
                    *(float2*)(out + (size_t)row * HID + colb) = o;
                }
            }
        }
    }
}

// ---------------- launch ----------------
extern "C" void kernel_launch(void* const* d_in, const int* in_sizes, int n_in,
                              void* d_out, int out_size)
{
    const int*   res_idx   = (const int*)d_in[0];
    const int*   ss_idx    = (const int*)d_in[1];
    const float* dist      = (const float*)d_in[2];
    const int*   seq_sep   = (const int*)d_in[3];
    const float* angles    = (const float*)d_in[4];
    const void*  validp    = d_in[5];
    const float* res_table = (const float*)d_in[6];
    const float* ss_table  = (const float*)d_in[7];
    const float* cont_W    = (const float*)d_in[8];
    const float* cont_b    = (const float*)d_in[9];
    const float* attn_W1   = (const float*)d_in[10];
    const float* attn_b1   = (const float*)d_in[11];
    const float* attn_W2   = (const float*)d_in[12];
    const float* attn_b2   = (const float*)d_in[13];
    const float* val_W1    = (const float*)d_in[14];
    const float* val_b1    = (const float*)d_in[15];
    const float* val_W2    = (const float*)d_in[16];
    const float* val_b2    = (const float*)d_in[17];
    const float* fallback  = (const float*)d_in[18];
    float* out = (float*)d_out;

    cudaFuncSetAttribute(fused_all, cudaFuncAttributeMaxDynamicSharedMemorySize, SMEM_BYTES);

    reset_flags<<<1, 1>>>();
    detect_valid<<<148, 1024>>>((const unsigned int*)validp, (B_TOTAL * KNB) / 4);
    prep_weights<<<148, 256>>>(attn_W1, val_W1, val_W2);

    fused_all<<<B_TOTAL / TILE_B, 512, SMEM_BYTES>>>(
        res_idx, ss_idx, dist, seq_sep, angles, validp,
        res_table, ss_table, cont_W, cont_b,
        attn_b1, attn_W2, attn_b2, val_b1, val_b2, fallback, out);
}

// round 7
// speedup vs baseline: 1.2141x; 1.2141x over previous
#include <cuda_runtime.h>
#include <math.h>

#define B_TOTAL 131072
#define KNB 5
#define TILE_B 16
#define ROWSF (TILE_B * KNB)   // 80
#define COMB 128
#define HID 256
#define AH 128
#define CLD 136                // comb stride (8g+2t conflict-free for LDS.64)
#define WLD 72                 // W1 chunk stride (64k pair-interleaved)
#define W2LD 40                // W2 chunk stride (32k pair-interleaved)
#define HLD 264                // hbar stride

typedef unsigned int uint32;

// ---------------- device globals (weights pre-converted, pre-transposed, k-pair-permuted) ----------------
__device__ uint32 g_w1aT[AH * COMB];        // [n=128][k'=128]
__device__ uint32 g_w1vT[HID * COMB];       // [n=256][k'=128]
__device__ uint32 g_w2T[HID * HID];         // [n=256][k'=256]
__device__ int g_flag_u8, g_flag_f32;

// ---------------- helpers ----------------
__device__ __forceinline__ uint32 f2tf(float f) {
    uint32 r; asm("cvt.rna.tf32.f32 %0, %1;" : "=r"(r) : "f"(f)); return r;
}
__device__ __forceinline__ void mma_tf32(float d[4], const uint32 a[4], const uint32 b[2]) {
    asm("mma.sync.aligned.m16n8k8.row.col.f32.tf32.tf32.f32 "
        "{%0,%1,%2,%3}, {%4,%5,%6,%7}, {%8,%9}, {%0,%1,%2,%3};"
        : "+f"(d[0]), "+f"(d[1]), "+f"(d[2]), "+f"(d[3])
        : "r"(a[0]), "r"(a[1]), "r"(a[2]), "r"(a[3]), "r"(b[0]), "r"(b[1]));
}
__device__ __forceinline__ float gelu_exact(float x) {
    return 0.5f * x * (1.0f + erff(x * 0.70710678118654752f));
}
// k-pair permute within each 8-block: [0,4,1,5,2,6,3,7] -> positions
__device__ __forceinline__ int kperm(int k) {
    return (k & ~7) | ((k & 3) << 1) | ((k & 4) >> 2);
}

// ---------------- prep: convert + transpose + permute weights ----------------
__global__ void prep_weights(const float* __restrict__ attn_W1,
                             const float* __restrict__ val_W1,
                             const float* __restrict__ val_W2) {
    int tid = blockIdx.x * blockDim.x + threadIdx.x;
    int stride = gridDim.x * blockDim.x;
    for (int i = tid; i < AH * COMB; i += stride) {
        int n = i >> 7, k = i & 127;
        g_w1aT[(n << 7) + kperm(k)] = f2tf(attn_W1[k * AH + n]);
    }
    for (int i = tid; i < HID * COMB; i += stride) {
        int n = i >> 7, k = i & 127;
        g_w1vT[(n << 7) + kperm(k)] = f2tf(val_W1[k * HID + n]);
    }
    for (int i = tid; i < HID * HID; i += stride) {
        int n = i >> 8, k = i & 255;
        g_w2T[(n << 8) + kperm(k)] = f2tf(val_W2[k * HID + n]);
    }
}

// ---------------- valid-dtype probe ----------------
__global__ void reset_flags() { g_flag_u8 = 0; g_flag_f32 = 0; }

__global__ void detect_valid(const unsigned int* __restrict__ v, int n) {
    int f8 = 0, f32 = 0;
    for (int i = blockIdx.x * blockDim.x + threadIdx.x; i < n; i += gridDim.x * blockDim.x) {
        unsigned int w = v[i];
        if (w == 0x3F800000u) f32 = 1;
        else if (w > 1u) f8 = 1;
    }
    if (__syncthreads_or(f8) && threadIdx.x == 0) atomicOr(&g_flag_u8, 1);
    if (__syncthreads_or(f32) && threadIdx.x == 0) atomicOr(&g_flag_f32, 1);
}

// ---------------- fused kernel smem layout (floats) ----------------
// comb @0: 80*136=10880 | Wbuf @10880: 10240 | hbar @21120: 16*264=4224
// P @25344: 720 | feat @26064: 480 | score @26544: 80 | wgt @26624: 80
// biasA @26704: 128 | w2a @26832: 128 | biasV @26960: 256 | b2s @27216: 256
// fbs @27472: 256 | cWs @27728: 192 | cbs @27920: 32 | ridx @27952: 80
// sidx @28032: 80 | anyv @28112: 16  -> 28128 floats = 112512 B (2 CTAs/SM)
#define SMEM_BYTES 112512

__global__ void __launch_bounds__(256, 2) fused_all(
    const int* __restrict__ res_idx,
    const int* __restrict__ ss_idx,
    const float* __restrict__ dist,
    const int* __restrict__ seq_sep,
    const float* __restrict__ angles,
    const void* __restrict__ validp,
    const float* __restrict__ res_table,
    const float* __restrict__ ss_table,
    const float* __restrict__ cont_W,
    const float* __restrict__ cont_b,
    const float* __restrict__ attn_b1,
    const float* __restrict__ attn_W2,
    const float* __restrict__ attn_b2,
    const float* __restrict__ val_b1,
    const float* __restrict__ val_b2,
    const float* __restrict__ fallback,
    float* __restrict__ out)
{
    extern __shared__ float sm[];
    float* comb    = sm;
    float* Wbuf    = sm + 10880;
    float* hbar_s  = sm + 21120;
    float* P       = sm + 25344;
    float* feat    = sm + 26064;
    float* score_s = sm + 26544;
    float* wgt_s   = sm + 26624;
    float* biasA   = sm + 26704;
    float* w2a_s   = sm + 26832;
    float* biasV   = sm + 26960;
    float* b2s     = sm + 27216;
    float* fbs     = sm + 27472;
    float* cWs     = sm + 27728;
    float* cbs     = sm + 27920;
    int*   ridx    = (int*)(sm + 27952);
    int*   sidx    = (int*)(sm + 28032);
    int*   anyv_s  = (int*)(sm + 28112);

    const int tid  = threadIdx.x;
    const int lane = tid & 31;
    const int warp = tid >> 5;      // 0..7
    const int g    = lane >> 2;     // 0..7
    const int t    = lane & 3;      // 0..3
    const int nb   = warp * 16;     // GEMM1/2 col base
    const int b0   = blockIdx.x * TILE_B;
    const int gr0  = b0 * KNB;

    const uint32* combu = (const uint32*)comb;
    const uint32* wsu   = (const uint32*)Wbuf;
    const uint32* hbU   = (const uint32*)hbar_s;

    // ---------- phase 0: constants + features ----------
    for (int i = tid; i < 192; i += 256) cWs[i] = cont_W[i];
    if (tid < 32) cbs[tid] = cont_b[tid];
    if (tid < AH) { biasA[tid] = attn_b1[tid]; w2a_s[tid] = attn_W2[tid]; }
    if (tid < HID) { biasV[tid] = val_b1[tid]; b2s[tid] = val_b2[tid]; fbs[tid] = fallback[tid]; }
    if (tid < ROWSF) {
        int gr = gr0 + tid;
        ridx[tid] = res_idx[gr];
        sidx[tid] = ss_idx[gr];
        float d = dist[gr];
        if (d != d) d = 0.0f;
        feat[tid * 6 + 0] = d * (1.0f / 15.0f);
        feat[tid * 6 + 1] = log1pf(fabsf((float)seq_sep[gr])) * 0.2f;
        float4 a = ((const float4*)angles)[gr];
        feat[tid * 6 + 2] = (a.x != a.x) ? 0.0f : a.x;
        feat[tid * 6 + 3] = (a.y != a.y) ? 0.0f : a.y;
        feat[tid * 6 + 4] = (a.z != a.z) ? 0.0f : a.z;
        feat[tid * 6 + 5] = (a.w != a.w) ? 0.0f : a.w;
    }
    __syncthreads();

    // ---------- phase 1: build comb, row perm rt=(j%5)*16+(j/5), col perm kperm(c) ----------
    for (int i = tid; i < ROWSF * 16; i += 256) {          // res: 16 float4 per row
        int j = i >> 4, q = i & 15;
        int rt = (j % 5) * 16 + (j / 5);
        float4 v = ((const float4*)res_table)[ridx[j] * 16 + q];
        float* cr = comb + rt * CLD;
        int c = q * 4;
        cr[kperm(c)]     = __uint_as_float(f2tf(v.x));
        cr[kperm(c + 1)] = __uint_as_float(f2tf(v.y));
        cr[kperm(c + 2)] = __uint_as_float(f2tf(v.z));
        cr[kperm(c + 3)] = __uint_as_float(f2tf(v.w));
    }
    for (int i = tid; i < ROWSF * 8; i += 256) {           // ss: 8 float4 per row
        int j = i >> 3, q = i & 7;
        int rt = (j % 5) * 16 + (j / 5);
        float4 v = ((const float4*)ss_table)[sidx[j] * 8 + q];
        float* cr = comb + rt * CLD;
        int c = 64 + q * 4;
        cr[kperm(c)]     = __uint_as_float(f2tf(v.x));
        cr[kperm(c + 1)] = __uint_as_float(f2tf(v.y));
        cr[kperm(c + 2)] = __uint_as_float(f2tf(v.z));
        cr[kperm(c + 3)] = __uint_as_float(f2tf(v.w));
    }
    for (int i = tid; i < ROWSF * 32; i += 256) {          // cont: scalar
        int j = i >> 5, c = i & 31;
        int rt = (j % 5) * 16 + (j / 5);
        float s = cbs[c];
        #pragma unroll
        for (int jj = 0; jj < 6; jj++) s += feat[j * 6 + jj] * cWs[jj * 32 + c];
        comb[rt * CLD + kperm(96 + c)] = __uint_as_float(f2tf(s));
    }
    __syncthreads();

    // ---------- phase 2: GEMM1 (attention scores), K in 2 chunks of 64 ----------
    {
        float acc[5][2][4];
        #pragma unroll
        for (int mi = 0; mi < 5; mi++)
            #pragma unroll
            for (int ni = 0; ni < 2; ni++)
                #pragma unroll
                for (int q = 0; q < 4; q++) acc[mi][ni][q] = 0.0f;

        #pragma unroll 1
        for (int kc = 0; kc < 2; kc++) {
            __syncthreads();
            for (int i = tid; i < AH * 16; i += 256) {      // stage 128n x 64k'
                int n = i >> 4, q = i & 15;
                ((float4*)(Wbuf + n * WLD))[q] = ((const float4*)g_w1aT)[n * 32 + kc * 16 + q];
            }
            __syncthreads();
            #pragma unroll
            for (int ks = 0; ks < 8; ks++) {
                int kb = ks * 8;
                uint32 a[5][4];
                #pragma unroll
                for (int mi = 0; mi < 5; mi++) {
                    const uint32* base = combu + (mi * 16 + g) * CLD + kc * 64 + kb + 2 * t;
                    uint2 p0 = *(const uint2*)base;
                    uint2 p1 = *(const uint2*)(base + 8 * CLD);
                    a[mi][0] = p0.x; a[mi][2] = p0.y;
                    a[mi][1] = p1.x; a[mi][3] = p1.y;
                }
                uint32 bb[2][2];
                #pragma unroll
                for (int ni = 0; ni < 2; ni++) {
                    uint2 pb = *(const uint2*)(wsu + (nb + ni * 8 + g) * WLD + kb + 2 * t);
                    bb[ni][0] = pb.x; bb[ni][1] = pb.y;
                }
                #pragma unroll
                for (int mi = 0; mi < 5; mi++)
                    #pragma unroll
                    for (int ni = 0; ni < 2; ni++)
                        mma_tf32(acc[mi][ni], a[mi], bb[ni]);
            }
        }
        #pragma unroll
        for (int mi = 0; mi < 5; mi++) {
            #pragma unroll
            for (int rh = 0; rh < 2; rh++) {
                int row = mi * 16 + g + 8 * rh;
                float p = 0.0f;
                #pragma unroll
                for (int ni = 0; ni < 2; ni++) {
                    #pragma unroll
                    for (int c = 0; c < 2; c++) {
                        int col = nb + ni * 8 + 2 * t + c;
                        p += gelu_exact(acc[mi][ni][rh * 2 + c] + biasA[col]) * w2a_s[col];
                    }
                }
                p += __shfl_xor_sync(0xFFFFFFFFu, p, 1);
                p += __shfl_xor_sync(0xFFFFFFFFu, p, 2);
                if (t == 0) P[row * 9 + warp] = p;
            }
        }
    }
    __syncthreads();
    if (tid < ROWSF) {
        float s = 0.0f;
        #pragma unroll
        for (int w = 0; w < 8; w++) s += P[tid * 9 + w];
        score_s[tid] = s;
    }
    __syncthreads();

    // ---------- phase 3: softmax (tid<16, rows rt=k*16+b) ----------
    if (tid < TILE_B) {
        int gb = b0 + tid;
        float ab2 = attn_b2[0];
        int fu8 = g_flag_u8, ff32 = g_flag_f32;
        float s[KNB];
        int any = 0;
        #pragma unroll
        for (int k = 0; k < KNB; k++) {
            int idx = gb * KNB + k;
            int v;
            if (ff32)      v = (((const float*)validp)[idx] != 0.0f);
            else if (fu8)  v = (((const unsigned char*)validp)[idx] != 0);
            else           v = (((const int*)validp)[idx] != 0);
            any |= v;
            s[k] = v ? (score_s[k * 16 + tid] + ab2) : -10000.0f;
        }
        float m = s[0];
        #pragma unroll
        for (int k = 1; k < KNB; k++) m = fmaxf(m, s[k]);
        float e[KNB], sum = 0.0f;
        #pragma unroll
        for (int k = 0; k < KNB; k++) { e[k] = expf(s[k] - m); sum += e[k]; }
        float inv = 1.0f / sum;
        #pragma unroll
        for (int k = 0; k < KNB; k++) wgt_s[k * 16 + tid] = e[k] * inv;
        anyv_s[tid] = any;
    }

    // ---------- phases 4-5: GEMM2 halves -> hbar (register-local weighted reduce) ----------
    #pragma unroll 1
    for (int half = 0; half < 2; half++) {
        float acc[5][2][4];
        #pragma unroll
        for (int mi = 0; mi < 5; mi++)
            #pragma unroll
            for (int ni = 0; ni < 2; ni++)
                #pragma unroll
                for (int q = 0; q < 4; q++) acc[mi][ni][q] = 0.0f;

        #pragma unroll 1
        for (int kc = 0; kc < 2; kc++) {
            __syncthreads();
            for (int i = tid; i < 128 * 16; i += 256) {
                int n = i >> 4, q = i & 15;
                ((float4*)(Wbuf + n * WLD))[q] = ((const float4*)g_w1vT)[(half * 128 + n) * 32 + kc * 16 + q];
            }
            __syncthreads();
            #pragma unroll
            for (int ks = 0; ks < 8; ks++) {
                int kb = ks * 8;
                uint32 a[5][4];
                #pragma unroll
                for (int mi = 0; mi < 5; mi++) {
                    const uint32* base = combu + (mi * 16 + g) * CLD + kc * 64 + kb + 2 * t;
                    uint2 p0 = *(const uint2*)base;
                    uint2 p1 = *(const uint2*)(base + 8 * CLD);
                    a[mi][0] = p0.x; a[mi][2] = p0.y;
                    a[mi][1] = p1.x; a[mi][3] = p1.y;
                }
                uint32 bb[2][2];
                #pragma unroll
                for (int ni = 0; ni < 2; ni++) {
                    uint2 pb = *(const uint2*)(wsu + (nb + ni * 8 + g) * WLD + kb + 2 * t);
                    bb[ni][0] = pb.x; bb[ni][1] = pb.y;
                }
                #pragma unroll
                for (int mi = 0; mi < 5; mi++)
                    #pragma unroll
                    for (int ni = 0; ni < 2; ni++)
                        mma_tf32(acc[mi][ni], a[mi], bb[ni]);
            }
        }
        // epilogue: row = mi*16 + g + 8rh = k*16 + b with k=mi, b=g+8rh
        float hb[2][4];
        #pragma unroll
        for (int rh = 0; rh < 2; rh++)
            #pragma unroll
            for (int cc = 0; cc < 4; cc++) hb[rh][cc] = 0.0f;
        #pragma unroll
        for (int mi = 0; mi < 5; mi++) {
            #pragma unroll
            for (int rh = 0; rh < 2; rh++) {
                float wk = wgt_s[mi * 16 + g + 8 * rh];
                #pragma unroll
                for (int ni = 0; ni < 2; ni++) {
                    #pragma unroll
                    for (int c = 0; c < 2; c++) {
                        int col = nb + ni * 8 + 2 * t + c;
                        hb[rh][ni * 2 + c] += wk * gelu_exact(acc[mi][ni][rh * 2 + c] + biasV[half * 128 + col]);
                    }
                }
            }
        }
        #pragma unroll
        for (int rh = 0; rh < 2; rh++) {
            int b = g + 8 * rh;
            #pragma unroll
            for (int ni = 0; ni < 2; ni++)
                #pragma unroll
                for (int c = 0; c < 2; c++) {
                    int col = nb + ni * 8 + 2 * t + c;
                    hbar_s[b * HLD + half * 128 + kperm(col)] = __uint_as_float(f2tf(hb[rh][ni * 2 + c]));
                }
        }
    }
    __syncthreads();

    // ---------- phase 6: output GEMM (16 x 256) @ (256 x 256), K in 8 chunks of 32 ----------
    {
        const int nb2 = warp * 32;
        float acc[4][4];
        #pragma unroll
        for (int ni = 0; ni < 4; ni++)
            #pragma unroll
            for (int q = 0; q < 4; q++) acc[ni][q] = 0.0f;

        #pragma unroll 1
        for (int kc = 0; kc < 8; kc++) {
            __syncthreads();
            for (int i = tid; i < 256 * 8; i += 256) {     // stage 256n x 32k'
                int n = i >> 3, q = i & 7;
                ((float4*)(Wbuf + n * W2LD))[q] = ((const float4*)g_w2T)[n * 64 + kc * 8 + q];
            }
            __syncthreads();
            #pragma unroll
            for (int ks = 0; ks < 4; ks++) {
                int kb = ks * 8;
                uint32 a[4];
                {
                    const uint32* base = hbU + g * HLD + kc * 32 + kb + 2 * t;
                    uint2 p0 = *(const uint2*)base;
                    uint2 p1 = *(const uint2*)(base + 8 * HLD);
                    a[0] = p0.x; a[2] = p0.y;
                    a[1] = p1.x; a[3] = p1.y;
                }
                #pragma unroll
                for (int ni = 0; ni < 4; ni++) {
                    uint2 pb = *(const uint2*)(wsu + (nb2 + ni * 8 + g) * W2LD + kb + 2 * t);
                    uint32 bb[2] = {pb.x, pb.y};
                    mma_tf32(acc[ni], a, bb);
                }
            }
        }

        #pragma unroll
        for (int rh = 0; rh < 2; rh++) {
            int b = g + 8 * rh;
            int av = anyv_s[b];
            int row = b0 + b;
            #pragma unroll
            for (int ni = 0; ni < 4; ni++) {
                int colb = nb2 + ni * 8 + 2 * t;
                float x0 = acc[ni][rh * 2 + 0];
                float x1 = acc[ni][rh * 2 + 1];
                float2 o;
                if (av) { o.x = x0 + b2s[colb]; o.y = x1 + b2s[colb + 1]; }
                else    { o.x = fbs[colb];      o.y = fbs[colb + 1]; }
                *(float2*)(out + (size_t)row * HID + colb) = o;
            }
        }
    }
}

// ---------------- launch ----------------
extern "C" void kernel_launch(void* const* d_in, const int* in_sizes, int n_in,
                              void* d_out, int out_size)
{
    const int*   res_idx   = (const int*)d_in[0];
    const int*   ss_idx    = (const int*)d_in[1];
    const float* dist      = (const float*)d_in[2];
    const int*   seq_sep   = (const int*)d_in[3];
    const float* angles    = (const float*)d_in[4];
    const void*  validp    = d_in[5];
    const float* res_table = (const float*)d_in[6];
    const float* ss_table  = (const float*)d_in[7];
    const float* cont_W    = (const float*)d_in[8];
    const float* cont_b    = (const float*)d_in[9];
    const float* attn_W1   = (const float*)d_in[10];
    const float* attn_b1   = (const float*)d_in[11];
    const float* attn_W2   = (const float*)d_in[12];
    const float* attn_b2   = (const float*)d_in[13];
    const float* val_W1    = (const float*)d_in[14];
    const float* val_b1    = (const float*)d_in[15];
    const float* val_W2    = (const float*)d_in[16];
    const float* val_b2    = (const float*)d_in[17];
    const float* fallback  = (const float*)d_in[18];
    float* out = (float*)d_out;

    cudaFuncSetAttribute(fused_all, cudaFuncAttributeMaxDynamicSharedMemorySize, SMEM_BYTES);

    reset_flags<<<1, 1>>>();
    detect_valid<<<148, 1024>>>((const unsigned int*)validp, (B_TOTAL * KNB) / 4);
    prep_weights<<<148, 256>>>(attn_W1, val_W1, val_W2);

    fused_all<<<B_TOTAL / TILE_B, 256, SMEM_BYTES>>>(
        res_idx, ss_idx, dist, seq_sep, angles, validp,
        res_table, ss_table, cont_W, cont_b,
        attn_b1, attn_W2, attn_b2, val_b1, val_b2, fallback, out);
}

// round 8
// speedup vs baseline: 1.2863x; 1.0595x over previous
#include <cuda_runtime.h>
#include <math.h>

#define B_TOTAL 131072
#define KNB 5
#define TILE_B 16
#define ROWSF (TILE_B * KNB)   // 80
#define COMB 128
#define HID 256
#define AH 128
#define CLD 136                // comb stride (8g+2t conflict-free LDS.64)
#define HLD 264                // hbar stride

typedef unsigned int uint32;

// ---------------- device globals (weights tf32, transposed [n][k'], k-pair-permuted) ----------------
__device__ uint32 g_w1aT[AH * COMB];        // [n=128][k'=128]
__device__ uint32 g_w1vT[HID * COMB];       // [n=256][k'=128]
__device__ uint32 g_w2T[HID * HID];         // [n=256][k'=256]
__device__ int g_flag_u8, g_flag_f32;

// ---------------- helpers ----------------
__device__ __forceinline__ uint32 f2tf(float f) {
    uint32 r; asm("cvt.rna.tf32.f32 %0, %1;" : "=r"(r) : "f"(f)); return r;
}
__device__ __forceinline__ void mma_tf32(float d[4], const uint32 a[4], const uint32 b[2]) {
    asm("mma.sync.aligned.m16n8k8.row.col.f32.tf32.tf32.f32 "
        "{%0,%1,%2,%3}, {%4,%5,%6,%7}, {%8,%9}, {%0,%1,%2,%3};"
        : "+f"(d[0]), "+f"(d[1]), "+f"(d[2]), "+f"(d[3])
        : "r"(a[0]), "r"(a[1]), "r"(a[2]), "r"(a[3]), "r"(b[0]), "r"(b[1]));
}
__device__ __forceinline__ float gelu_exact(float x) {
    return 0.5f * x * (1.0f + erff(x * 0.70710678118654752f));
}
// k-pair permute within each 8-block: value k goes to slot [0,4->0,1 ; 1,5->2,3 ; ...]
__device__ __forceinline__ int kperm(int k) {
    return (k & ~7) | ((k & 3) << 1) | ((k & 4) >> 2);
}

// ---------------- prep: convert + transpose + permute weights ----------------
__global__ void prep_weights(const float* __restrict__ attn_W1,
                             const float* __restrict__ val_W1,
                             const float* __restrict__ val_W2) {
    int tid = blockIdx.x * blockDim.x + threadIdx.x;
    int stride = gridDim.x * blockDim.x;
    for (int i = tid; i < AH * COMB; i += stride) {
        int n = i >> 7, k = i & 127;
        g_w1aT[(n << 7) + kperm(k)] = f2tf(attn_W1[k * AH + n]);
    }
    for (int i = tid; i < HID * COMB; i += stride) {
        int n = i >> 7, k = i & 127;
        g_w1vT[(n << 7) + kperm(k)] = f2tf(val_W1[k * HID + n]);
    }
    for (int i = tid; i < HID * HID; i += stride) {
        int n = i >> 8, k = i & 255;
        g_w2T[(n << 8) + kperm(k)] = f2tf(val_W2[k * HID + n]);
    }
}

// ---------------- valid-dtype probe ----------------
__global__ void reset_flags() { g_flag_u8 = 0; g_flag_f32 = 0; }

__global__ void detect_valid(const unsigned int* __restrict__ v, int n) {
    int f8 = 0, f32 = 0;
    for (int i = blockIdx.x * blockDim.x + threadIdx.x; i < n; i += gridDim.x * blockDim.x) {
        unsigned int w = v[i];
        if (w == 0x3F800000u) f32 = 1;
        else if (w > 1u) f8 = 1;
    }
    if (__syncthreads_or(f8) && threadIdx.x == 0) atomicOr(&g_flag_u8, 1);
    if (__syncthreads_or(f32) && threadIdx.x == 0) atomicOr(&g_flag_f32, 1);
}

// ---------------- fused kernel smem layout (floats) ----------------
// comb @0: 80*136=10880 | hbar @10880: 16*264=4224 | P @15104: 720
// feat @15824: 480 | score @16304: 80 | wgt @16384: 80 | biasA @16464: 128
// w2a @16592: 128 | biasV @16720: 256 | b2s @16976: 256 | fbs @17232: 256
// cWs @17488: 192 | cbs @17680: 32 | ridx @17712: 80 | sidx @17792: 80
// anyv @17872: 16  -> 17888 floats = 71552 B  (3 CTAs/SM)
#define SMEM_BYTES 71552

__global__ void __launch_bounds__(256, 3) fused_all(
    const int* __restrict__ res_idx,
    const int* __restrict__ ss_idx,
    const float* __restrict__ dist,
    const int* __restrict__ seq_sep,
    const float* __restrict__ angles,
    const void* __restrict__ validp,
    const float* __restrict__ res_table,
    const float* __restrict__ ss_table,
    const float* __restrict__ cont_W,
    const float* __restrict__ cont_b,
    const float* __restrict__ attn_b1,
    const float* __restrict__ attn_W2,
    const float* __restrict__ attn_b2,
    const float* __restrict__ val_b1,
    const float* __restrict__ val_b2,
    const float* __restrict__ fallback,
    float* __restrict__ out)
{
    extern __shared__ float sm[];
    float* comb    = sm;
    float* hbar_s  = sm + 10880;
    float* P       = sm + 15104;
    float* feat    = sm + 15824;
    float* score_s = sm + 16304;
    float* wgt_s   = sm + 16384;
    float* biasA   = sm + 16464;
    float* w2a_s   = sm + 16592;
    float* biasV   = sm + 16720;
    float* b2s     = sm + 16976;
    float* fbs     = sm + 17232;
    float* cWs     = sm + 17488;
    float* cbs     = sm + 17680;
    int*   ridx    = (int*)(sm + 17712);
    int*   sidx    = (int*)(sm + 17792);
    int*   anyv_s  = (int*)(sm + 17872);

    const int tid  = threadIdx.x;
    const int lane = tid & 31;
    const int warp = tid >> 5;      // 0..7
    const int g    = lane >> 2;     // 0..7
    const int t    = lane & 3;      // 0..3
    const int nb   = warp * 16;     // GEMM1/2 col base
    const int b0   = blockIdx.x * TILE_B;
    const int gr0  = b0 * KNB;

    const uint32* combu = (const uint32*)comb;
    const uint32* hbU   = (const uint32*)hbar_s;
    const uint2*  w1a2  = (const uint2*)g_w1aT;
    const uint2*  w1v2  = (const uint2*)g_w1vT;
    const uint2*  w22   = (const uint2*)g_w2T;

    // ---------- phase 0: constants + features ----------
    for (int i = tid; i < 192; i += 256) cWs[i] = cont_W[i];
    if (tid < 32) cbs[tid] = cont_b[tid];
    if (tid < AH) { biasA[tid] = attn_b1[tid]; w2a_s[tid] = attn_W2[tid]; }
    if (tid < HID) { biasV[tid] = val_b1[tid]; b2s[tid] = val_b2[tid]; fbs[tid] = fallback[tid]; }
    if (tid < ROWSF) {
        int gr = gr0 + tid;
        ridx[tid] = res_idx[gr];
        sidx[tid] = ss_idx[gr];
        float d = dist[gr];
        if (d != d) d = 0.0f;
        feat[tid * 6 + 0] = d * (1.0f / 15.0f);
        feat[tid * 6 + 1] = log1pf(fabsf((float)seq_sep[gr])) * 0.2f;
        float4 a = ((const float4*)angles)[gr];
        feat[tid * 6 + 2] = (a.x != a.x) ? 0.0f : a.x;
        feat[tid * 6 + 3] = (a.y != a.y) ? 0.0f : a.y;
        feat[tid * 6 + 4] = (a.z != a.z) ? 0.0f : a.z;
        feat[tid * 6 + 5] = (a.w != a.w) ? 0.0f : a.w;
    }
    __syncthreads();

    // ---------- phase 1: build comb, row perm rt=(j%5)*16+(j/5), col perm kperm(c) ----------
    for (int i = tid; i < ROWSF * 16; i += 256) {          // res: 16 float4 per row
        int j = i >> 4, q = i & 15;
        int rt = (j % 5) * 16 + (j / 5);
        float4 v = ((const float4*)res_table)[ridx[j] * 16 + q];
        float* cr = comb + rt * CLD;
        int c = q * 4;
        cr[kperm(c)]     = __uint_as_float(f2tf(v.x));
        cr[kperm(c + 1)] = __uint_as_float(f2tf(v.y));
        cr[kperm(c + 2)] = __uint_as_float(f2tf(v.z));
        cr[kperm(c + 3)] = __uint_as_float(f2tf(v.w));
    }
    for (int i = tid; i < ROWSF * 8; i += 256) {           // ss: 8 float4 per row
        int j = i >> 3, q = i & 7;
        int rt = (j % 5) * 16 + (j / 5);
        float4 v = ((const float4*)ss_table)[sidx[j] * 8 + q];
        float* cr = comb + rt * CLD;
        int c = 64 + q * 4;
        cr[kperm(c)]     = __uint_as_float(f2tf(v.x));
        cr[kperm(c + 1)] = __uint_as_float(f2tf(v.y));
        cr[kperm(c + 2)] = __uint_as_float(f2tf(v.z));
        cr[kperm(c + 3)] = __uint_as_float(f2tf(v.w));
    }
    for (int i = tid; i < ROWSF * 32; i += 256) {          // cont: scalar
        int j = i >> 5, c = i & 31;
        int rt = (j % 5) * 16 + (j / 5);
        float s = cbs[c];
        #pragma unroll
        for (int jj = 0; jj < 6; jj++) s += feat[j * 6 + jj] * cWs[jj * 32 + c];
        comb[rt * CLD + kperm(96 + c)] = __uint_as_float(f2tf(s));
    }
    __syncthreads();

    // ---------- phase 2: GEMM1 (attention scores), B direct from gmem ----------
    {
        float acc[5][2][4];
        #pragma unroll
        for (int mi = 0; mi < 5; mi++)
            #pragma unroll
            for (int ni = 0; ni < 2; ni++)
                #pragma unroll
                for (int q = 0; q < 4; q++) acc[mi][ni][q] = 0.0f;

        #pragma unroll 2
        for (int ks = 0; ks < 16; ks++) {
            int kb = ks * 8;
            uint32 bbr[2][2];
            #pragma unroll
            for (int ni = 0; ni < 2; ni++) {
                uint2 pb = __ldg(w1a2 + ((nb + ni * 8 + g) << 6) + (kb >> 1) + t);
                bbr[ni][0] = pb.x; bbr[ni][1] = pb.y;
            }
            uint32 a[5][4];
            #pragma unroll
            for (int mi = 0; mi < 5; mi++) {
                const uint32* base = combu + (mi * 16 + g) * CLD + kb + 2 * t;
                uint2 p0 = *(const uint2*)base;
                uint2 p1 = *(const uint2*)(base + 8 * CLD);
                a[mi][0] = p0.x; a[mi][2] = p0.y;
                a[mi][1] = p1.x; a[mi][3] = p1.y;
            }
            #pragma unroll
            for (int mi = 0; mi < 5; mi++)
                #pragma unroll
                for (int ni = 0; ni < 2; ni++)
                    mma_tf32(acc[mi][ni], a[mi], bbr[ni]);
        }
        #pragma unroll
        for (int mi = 0; mi < 5; mi++) {
            #pragma unroll
            for (int rh = 0; rh < 2; rh++) {
                int row = mi * 16 + g + 8 * rh;
                float p = 0.0f;
                #pragma unroll
                for (int ni = 0; ni < 2; ni++) {
                    #pragma unroll
                    for (int c = 0; c < 2; c++) {
                        int col = nb + ni * 8 + 2 * t + c;
                        p += gelu_exact(acc[mi][ni][rh * 2 + c] + biasA[col]) * w2a_s[col];
                    }
                }
                p += __shfl_xor_sync(0xFFFFFFFFu, p, 1);
                p += __shfl_xor_sync(0xFFFFFFFFu, p, 2);
                if (t == 0) P[row * 9 + warp] = p;
            }
        }
    }
    __syncthreads();
    if (tid < ROWSF) {
        float s = 0.0f;
        #pragma unroll
        for (int w = 0; w < 8; w++) s += P[tid * 9 + w];
        score_s[tid] = s;
    }
    __syncthreads();

    // ---------- phase 3: softmax (tid<16, rows rt=k*16+b) ----------
    if (tid < TILE_B) {
        int gb = b0 + tid;
        float ab2 = attn_b2[0];
        int fu8 = g_flag_u8, ff32 = g_flag_f32;
        float s[KNB];
        int any = 0;
        #pragma unroll
        for (int k = 0; k < KNB; k++) {
            int idx = gb * KNB + k;
            int v;
            if (ff32)      v = (((const float*)validp)[idx] != 0.0f);
            else if (fu8)  v = (((const unsigned char*)validp)[idx] != 0);
            else           v = (((const int*)validp)[idx] != 0);
            any |= v;
            s[k] = v ? (score_s[k * 16 + tid] + ab2) : -10000.0f;
        }
        float m = s[0];
        #pragma unroll
        for (int k = 1; k < KNB; k++) m = fmaxf(m, s[k]);
        float e[KNB], sum = 0.0f;
        #pragma unroll
        for (int k = 0; k < KNB; k++) { e[k] = expf(s[k] - m); sum += e[k]; }
        float inv = 1.0f / sum;
        #pragma unroll
        for (int k = 0; k < KNB; k++) wgt_s[k * 16 + tid] = e[k] * inv;
        anyv_s[tid] = any;
    }
    __syncthreads();

    // ---------- phases 4-5: GEMM2 halves -> hbar, B direct from gmem ----------
    #pragma unroll 1
    for (int half = 0; half < 2; half++) {
        float acc[5][2][4];
        #pragma unroll
        for (int mi = 0; mi < 5; mi++)
            #pragma unroll
            for (int ni = 0; ni < 2; ni++)
                #pragma unroll
                for (int q = 0; q < 4; q++) acc[mi][ni][q] = 0.0f;

        #pragma unroll 2
        for (int ks = 0; ks < 16; ks++) {
            int kb = ks * 8;
            uint32 bbr[2][2];
            #pragma unroll
            for (int ni = 0; ni < 2; ni++) {
                uint2 pb = __ldg(w1v2 + ((half * 128 + nb + ni * 8 + g) << 6) + (kb >> 1) + t);
                bbr[ni][0] = pb.x; bbr[ni][1] = pb.y;
            }
            uint32 a[5][4];
            #pragma unroll
            for (int mi = 0; mi < 5; mi++) {
                const uint32* base = combu + (mi * 16 + g) * CLD + kb + 2 * t;
                uint2 p0 = *(const uint2*)base;
                uint2 p1 = *(const uint2*)(base + 8 * CLD);
                a[mi][0] = p0.x; a[mi][2] = p0.y;
                a[mi][1] = p1.x; a[mi][3] = p1.y;
            }
            #pragma unroll
            for (int mi = 0; mi < 5; mi++)
                #pragma unroll
                for (int ni = 0; ni < 2; ni++)
                    mma_tf32(acc[mi][ni], a[mi], bbr[ni]);
        }
        // epilogue: row = mi*16 + g + 8rh = k*16 + b ; register-local weighted 5:1 reduce
        float hb[2][4];
        #pragma unroll
        for (int rh = 0; rh < 2; rh++)
            #pragma unroll
            for (int cc = 0; cc < 4; cc++) hb[rh][cc] = 0.0f;
        #pragma unroll
        for (int mi = 0; mi < 5; mi++) {
            #pragma unroll
            for (int rh = 0; rh < 2; rh++) {
                float wk = wgt_s[mi * 16 + g + 8 * rh];
                #pragma unroll
                for (int ni = 0; ni < 2; ni++) {
                    #pragma unroll
                    for (int c = 0; c < 2; c++) {
                        int col = nb + ni * 8 + 2 * t + c;
                        hb[rh][ni * 2 + c] += wk * gelu_exact(acc[mi][ni][rh * 2 + c] + biasV[half * 128 + col]);
                    }
                }
            }
        }
        #pragma unroll
        for (int rh = 0; rh < 2; rh++) {
            int b = g + 8 * rh;
            #pragma unroll
            for (int ni = 0; ni < 2; ni++)
                #pragma unroll
                for (int c = 0; c < 2; c++) {
                    int col = nb + ni * 8 + 2 * t + c;
                    hbar_s[b * HLD + half * 128 + kperm(col)] = __uint_as_float(f2tf(hb[rh][ni * 2 + c]));
                }
        }
    }
    __syncthreads();

    // ---------- phase 6: output GEMM (16 x 256) @ (256 x 256), B direct from gmem ----------
    {
        const int nb2 = warp * 32;
        float acc[4][4];
        #pragma unroll
        for (int ni = 0; ni < 4; ni++)
            #pragma unroll
            for (int q = 0; q < 4; q++) acc[ni][q] = 0.0f;

        #pragma unroll 4
        for (int ks = 0; ks < 32; ks++) {
            int kabs = ks * 8;
            uint32 a[4];
            {
                const uint32* base = hbU + g * HLD + kabs + 2 * t;
                uint2 p0 = *(const uint2*)base;
                uint2 p1 = *(const uint2*)(base + 8 * HLD);
                a[0] = p0.x; a[2] = p0.y;
                a[1] = p1.x; a[3] = p1.y;
            }
            #pragma unroll
            for (int ni = 0; ni < 4; ni++) {
                uint2 pb = __ldg(w22 + ((nb2 + ni * 8 + g) << 7) + (kabs >> 1) + t);
                uint32 bb[2] = {pb.x, pb.y};
                mma_tf32(acc[ni], a, bb);
            }
        }

        #pragma unroll
        for (int rh = 0; rh < 2; rh++) {
            int b = g + 8 * rh;
            int av = anyv_s[b];
            int row = b0 + b;
            #pragma unroll
            for (int ni = 0; ni < 4; ni++) {
                int colb = nb2 + ni * 8 + 2 * t;
                float x0 = acc[ni][rh * 2 + 0];
                float x1 = acc[ni][rh * 2 + 1];
                float2 o;
                if (av) { o.x = x0 + b2s[colb]; o.y = x1 + b2s[colb + 1]; }
                else    { o.x = fbs[colb];      o.y = fbs[colb + 1]; }
                *(float2*)(out + (size_t)row * HID + colb) = o;
            }
        }
    }
}

// ---------------- launch ----------------
extern "C" void kernel_launch(void* const* d_in, const int* in_sizes, int n_in,
                              void* d_out, int out_size)
{
    const int*   res_idx   = (const int*)d_in[0];
    const int*   ss_idx    = (const int*)d_in[1];
    const float* dist      = (const float*)d_in[2];
    const int*   seq_sep   = (const int*)d_in[3];
    const float* angles    = (const float*)d_in[4];
    const void*  validp    = d_in[5];
    const float* res_table = (const float*)d_in[6];
    const float* ss_table  = (const float*)d_in[7];
    const float* cont_W    = (const float*)d_in[8];
    const float* cont_b    = (const float*)d_in[9];
    const float* attn_W1   = (const float*)d_in[10];
    const float* attn_b1   = (const float*)d_in[11];
    const float* attn_W2   = (const float*)d_in[12];
    const float* attn_b2   = (const float*)d_in[13];
    const float* val_W1    = (const float*)d_in[14];
    const float* val_b1    = (const float*)d_in[15];
    const float* val_W2    = (const float*)d_in[16];
    const float* val_b2    = (const float*)d_in[17];
    const float* fallback  = (const float*)d_in[18];
    float* out = (float*)d_out;

    cudaFuncSetAttribute(fused_all, cudaFuncAttributeMaxDynamicSharedMemorySize, SMEM_BYTES);

    reset_flags<<<1, 1>>>();
    detect_valid<<<148, 1024>>>((const unsigned int*)validp, (B_TOTAL * KNB) / 4);
    prep_weights<<<148, 256>>>(attn_W1, val_W1, val_W2);

    fused_all<<<B_TOTAL / TILE_B, 256, SMEM_BYTES>>>(
        res_idx, ss_idx, dist, seq_sep, angles, validp,
        res_table, ss_table, cont_W, cont_b,
        attn_b1, attn_W2, attn_b2, val_b1, val_b2, fallback, out);
}

// round 9
// speedup vs baseline: 1.6022x; 1.2456x over previous
#include <cuda_runtime.h>
#include <math.h>

#define B_TOTAL 131072
#define KNB 5
#define TILE_B 16
#define ROWSF (TILE_B * KNB)   // 80
#define COMB 128
#define HID 256
#define AH 128
#define CLD 144                // comb stride (16 mod 32 -> conflict-free LDS.128 phases)
#define HLD 272                // hbar stride (16 mod 32)

typedef unsigned int uint32;

// ---------------- device globals (weights tf32, transposed [n][k'], k16-permuted) ----------------
__device__ uint32 g_w1aT[AH * COMB];        // [n=128][k'=128]
__device__ uint32 g_w1vT[HID * COMB];       // [n=256][k'=128]
__device__ uint32 g_w2T[HID * HID];         // [n=256][k'=256]
__device__ int g_flag_u8, g_flag_f32;

// ---------------- helpers ----------------
__device__ __forceinline__ uint32 f2tf(float f) {
    uint32 r; asm("cvt.rna.tf32.f32 %0, %1;" : "=r"(r) : "f"(f)); return r;
}
__device__ __forceinline__ void mma_tf32(float d[4], uint32 a0, uint32 a1, uint32 a2, uint32 a3,
                                         uint32 b0, uint32 b1) {
    asm("mma.sync.aligned.m16n8k8.row.col.f32.tf32.tf32.f32 "
        "{%0,%1,%2,%3}, {%4,%5,%6,%7}, {%8,%9}, {%0,%1,%2,%3};"
        : "+f"(d[0]), "+f"(d[1]), "+f"(d[2]), "+f"(d[3])
        : "r"(a0), "r"(a1), "r"(a2), "r"(a3), "r"(b0), "r"(b1));
}
__device__ __forceinline__ float gelu_exact(float x) {
    return 0.5f * x * (1.0f + erff(x * 0.70710678118654752f));
}
// 16-wide k permutation: k = c*8 + h*4 + t  ->  slot = 4t + 2c + h
__device__ __forceinline__ int kperm16(int k) {
    return (k & ~15) | ((k & 3) << 2) | ((k & 8) >> 2) | ((k & 4) >> 2);
}

// ---------------- prep: convert + transpose + permute weights ----------------
__global__ void prep_weights(const float* __restrict__ attn_W1,
                             const float* __restrict__ val_W1,
                             const float* __restrict__ val_W2) {
    int tid = blockIdx.x * blockDim.x + threadIdx.x;
    int stride = gridDim.x * blockDim.x;
    for (int i = tid; i < AH * COMB; i += stride) {
        int n = i >> 7, k = i & 127;
        g_w1aT[(n << 7) + kperm16(k)] = f2tf(attn_W1[k * AH + n]);
    }
    for (int i = tid; i < HID * COMB; i += stride) {
        int n = i >> 7, k = i & 127;
        g_w1vT[(n << 7) + kperm16(k)] = f2tf(val_W1[k * HID + n]);
    }
    for (int i = tid; i < HID * HID; i += stride) {
        int n = i >> 8, k = i & 255;
        g_w2T[(n << 8) + kperm16(k)] = f2tf(val_W2[k * HID + n]);
    }
}

// ---------------- valid-dtype probe ----------------
__global__ void reset_flags() { g_flag_u8 = 0; g_flag_f32 = 0; }

__global__ void detect_valid(const unsigned int* __restrict__ v, int n) {
    int f8 = 0, f32 = 0;
    for (int i = blockIdx.x * blockDim.x + threadIdx.x; i < n; i += gridDim.x * blockDim.x) {
        unsigned int w = v[i];
        if (w == 0x3F800000u) f32 = 1;
        else if (w > 1u) f8 = 1;
    }
    if (__syncthreads_or(f8) && threadIdx.x == 0) atomicOr(&g_flag_u8, 1);
    if (__syncthreads_or(f32) && threadIdx.x == 0) atomicOr(&g_flag_f32, 1);
}

// ---------------- fused kernel smem layout (floats) ----------------
// comb @0: 80*144=11520 | hbar @11520: 16*272=4352 | P @15872: 720
// feat @16592: 480 | score @17072: 80 | wgt @17152: 80 | biasA @17232: 128
// w2a @17360: 128 | biasV @17488: 256 | b2s @17744: 256 | fbs @18000: 256
// cWs @18256: 192 | cbs @18448: 32 | ridx @18480: 80 | sidx @18560: 80
// anyv @18640: 16  -> 18656 floats = 74624 B  (3 CTAs/SM = 223872 B)
#define SMEM_BYTES 74624

__global__ void __launch_bounds__(256, 3) fused_all(
    const int* __restrict__ res_idx,
    const int* __restrict__ ss_idx,
    const float* __restrict__ dist,
    const int* __restrict__ seq_sep,
    const float* __restrict__ angles,
    const void* __restrict__ validp,
    const float* __restrict__ res_table,
    const float* __restrict__ ss_table,
    const float* __restrict__ cont_W,
    const float* __restrict__ cont_b,
    const float* __restrict__ attn_b1,
    const float* __restrict__ attn_W2,
    const float* __restrict__ attn_b2,
    const float* __restrict__ val_b1,
    const float* __restrict__ val_b2,
    const float* __restrict__ fallback,
    float* __restrict__ out)
{
    extern __shared__ float sm[];
    float* comb    = sm;
    float* hbar_s  = sm + 11520;
    float* P       = sm + 15872;
    float* feat    = sm + 16592;
    float* score_s = sm + 17072;
    float* wgt_s   = sm + 17152;
    float* biasA   = sm + 17232;
    float* w2a_s   = sm + 17360;
    float* biasV   = sm + 17488;
    float* b2s     = sm + 17744;
    float* fbs     = sm + 18000;
    float* cWs     = sm + 18256;
    float* cbs     = sm + 18448;
    int*   ridx    = (int*)(sm + 18480);
    int*   sidx    = (int*)(sm + 18560);
    int*   anyv_s  = (int*)(sm + 18640);

    const int tid  = threadIdx.x;
    const int lane = tid & 31;
    const int warp = tid >> 5;      // 0..7
    const int g    = lane >> 2;     // 0..7
    const int t    = lane & 3;      // 0..3
    const int nb   = warp * 16;     // GEMM1/2 col base
    const int b0   = blockIdx.x * TILE_B;
    const int gr0  = b0 * KNB;

    const uint32* combu = (const uint32*)comb;
    const uint32* hbU   = (const uint32*)hbar_s;
    const uint4*  w1a4  = (const uint4*)g_w1aT;   // 32 uint4 per row
    const uint4*  w1v4  = (const uint4*)g_w1vT;   // 32 uint4 per row
    const uint4*  w24   = (const uint4*)g_w2T;    // 64 uint4 per row

    // ---------- phase 0: constants + features ----------
    for (int i = tid; i < 192; i += 256) cWs[i] = cont_W[i];
    if (tid < 32) cbs[tid] = cont_b[tid];
    if (tid < AH) { biasA[tid] = attn_b1[tid]; w2a_s[tid] = attn_W2[tid]; }
    if (tid < HID) { biasV[tid] = val_b1[tid]; b2s[tid] = val_b2[tid]; fbs[tid] = fallback[tid]; }
    if (tid < ROWSF) {
        int gr = gr0 + tid;
        ridx[tid] = res_idx[gr];
        sidx[tid] = ss_idx[gr];
        float d = dist[gr];
        if (d != d) d = 0.0f;
        feat[tid * 6 + 0] = d * (1.0f / 15.0f);
        feat[tid * 6 + 1] = log1pf(fabsf((float)seq_sep[gr])) * 0.2f;
        float4 a = ((const float4*)angles)[gr];
        feat[tid * 6 + 2] = (a.x != a.x) ? 0.0f : a.x;
        feat[tid * 6 + 3] = (a.y != a.y) ? 0.0f : a.y;
        feat[tid * 6 + 4] = (a.z != a.z) ? 0.0f : a.z;
        feat[tid * 6 + 5] = (a.w != a.w) ? 0.0f : a.w;
    }
    __syncthreads();

    // ---------- phase 1: build comb, row perm rt=(j%5)*16+(j/5), col perm kperm16(c) ----------
    for (int i = tid; i < ROWSF * 16; i += 256) {          // res: 16 float4 per row
        int j = i >> 4, q = i & 15;
        int rt = (j % 5) * 16 + (j / 5);
        float4 v = ((const float4*)res_table)[ridx[j] * 16 + q];
        float* cr = comb + rt * CLD;
        int c = q * 4;
        cr[kperm16(c)]     = __uint_as_float(f2tf(v.x));
        cr[kperm16(c + 1)] = __uint_as_float(f2tf(v.y));
        cr[kperm16(c + 2)] = __uint_as_float(f2tf(v.z));
        cr[kperm16(c + 3)] = __uint_as_float(f2tf(v.w));
    }
    for (int i = tid; i < ROWSF * 8; i += 256) {           // ss: 8 float4 per row
        int j = i >> 3, q = i & 7;
        int rt = (j % 5) * 16 + (j / 5);
        float4 v = ((const float4*)ss_table)[sidx[j] * 8 + q];
        float* cr = comb + rt * CLD;
        int c = 64 + q * 4;
        cr[kperm16(c)]     = __uint_as_float(f2tf(v.x));
        cr[kperm16(c + 1)] = __uint_as_float(f2tf(v.y));
        cr[kperm16(c + 2)] = __uint_as_float(f2tf(v.z));
        cr[kperm16(c + 3)] = __uint_as_float(f2tf(v.w));
    }
    for (int i = tid; i < ROWSF * 32; i += 256) {          // cont: scalar
        int j = i >> 5, c = i & 31;
        int rt = (j % 5) * 16 + (j / 5);
        float s = cbs[c];
        #pragma unroll
        for (int jj = 0; jj < 6; jj++) s += feat[j * 6 + jj] * cWs[jj * 32 + c];
        comb[rt * CLD + kperm16(96 + c)] = __uint_as_float(f2tf(s));
    }
    __syncthreads();

    // ---------- phase 2: GEMM1 (attention scores), 128-bit loads, 2 MMA chunks per load ----------
    {
        float acc[5][2][4];
        #pragma unroll
        for (int mi = 0; mi < 5; mi++)
            #pragma unroll
            for (int ni = 0; ni < 2; ni++)
                #pragma unroll
                for (int q = 0; q < 4; q++) acc[mi][ni][q] = 0.0f;

        #pragma unroll 2
        for (int ks = 0; ks < 8; ks++) {           // 16 k per iteration
            int kb = ks * 16;
            uint4 pb[2];
            #pragma unroll
            for (int ni = 0; ni < 2; ni++)
                pb[ni] = __ldg(w1a4 + (nb + ni * 8 + g) * 32 + ks * 4 + t);
            #pragma unroll
            for (int mi = 0; mi < 5; mi++) {
                const uint32* base = combu + (mi * 16 + g) * CLD + kb + 4 * t;
                uint4 pa0 = *(const uint4*)base;
                uint4 pa1 = *(const uint4*)(base + 8 * CLD);
                #pragma unroll
                for (int ni = 0; ni < 2; ni++) {
                    mma_tf32(acc[mi][ni], pa0.x, pa1.x, pa0.y, pa1.y, pb[ni].x, pb[ni].y);
                    mma_tf32(acc[mi][ni], pa0.z, pa1.z, pa0.w, pa1.w, pb[ni].z, pb[ni].w);
                }
            }
        }
        #pragma unroll
        for (int mi = 0; mi < 5; mi++) {
            #pragma unroll
            for (int rh = 0; rh < 2; rh++) {
                int row = mi * 16 + g + 8 * rh;
                float p = 0.0f;
                #pragma unroll
                for (int ni = 0; ni < 2; ni++) {
                    #pragma unroll
                    for (int c = 0; c < 2; c++) {
                        int col = nb + ni * 8 + 2 * t + c;
                        p += gelu_exact(acc[mi][ni][rh * 2 + c] + biasA[col]) * w2a_s[col];
                    }
                }
                p += __shfl_xor_sync(0xFFFFFFFFu, p, 1);
                p += __shfl_xor_sync(0xFFFFFFFFu, p, 2);
                if (t == 0) P[row * 9 + warp] = p;
            }
        }
    }
    __syncthreads();
    if (tid < ROWSF) {
        float s = 0.0f;
        #pragma unroll
        for (int w = 0; w < 8; w++) s += P[tid * 9 + w];
        score_s[tid] = s;
    }
    __syncthreads();

    // ---------- phase 3: softmax (tid<16, rows rt=k*16+b) ----------
    if (tid < TILE_B) {
        int gb = b0 + tid;
        float ab2 = attn_b2[0];
        int fu8 = g_flag_u8, ff32 = g_flag_f32;
        float s[KNB];
        int any = 0;
        #pragma unroll
        for (int k = 0; k < KNB; k++) {
            int idx = gb * KNB + k;
            int v;
            if (ff32)      v = (((const float*)validp)[idx] != 0.0f);
            else if (fu8)  v = (((const unsigned char*)validp)[idx] != 0);
            else           v = (((const int*)validp)[idx] != 0);
            any |= v;
            s[k] = v ? (score_s[k * 16 + tid] + ab2) : -10000.0f;
        }
        float m = s[0];
        #pragma unroll
        for (int k = 1; k < KNB; k++) m = fmaxf(m, s[k]);
        float e[KNB], sum = 0.0f;
        #pragma unroll
        for (int k = 0; k < KNB; k++) { e[k] = expf(s[k] - m); sum += e[k]; }
        float inv = 1.0f / sum;
        #pragma unroll
        for (int k = 0; k < KNB; k++) wgt_s[k * 16 + tid] = e[k] * inv;
        anyv_s[tid] = any;
    }
    __syncthreads();

    // ---------- phases 4-5: GEMM2 halves -> hbar ----------
    #pragma unroll 1
    for (int half = 0; half < 2; half++) {
        float acc[5][2][4];
        #pragma unroll
        for (int mi = 0; mi < 5; mi++)
            #pragma unroll
            for (int ni = 0; ni < 2; ni++)
                #pragma unroll
                for (int q = 0; q < 4; q++) acc[mi][ni][q] = 0.0f;

        #pragma unroll 2
        for (int ks = 0; ks < 8; ks++) {
            int kb = ks * 16;
            uint4 pb[2];
            #pragma unroll
            for (int ni = 0; ni < 2; ni++)
                pb[ni] = __ldg(w1v4 + (half * 128 + nb + ni * 8 + g) * 32 + ks * 4 + t);
            #pragma unroll
            for (int mi = 0; mi < 5; mi++) {
                const uint32* base = combu + (mi * 16 + g) * CLD + kb + 4 * t;
                uint4 pa0 = *(const uint4*)base;
                uint4 pa1 = *(const uint4*)(base + 8 * CLD);
                #pragma unroll
                for (int ni = 0; ni < 2; ni++) {
                    mma_tf32(acc[mi][ni], pa0.x, pa1.x, pa0.y, pa1.y, pb[ni].x, pb[ni].y);
                    mma_tf32(acc[mi][ni], pa0.z, pa1.z, pa0.w, pa1.w, pb[ni].z, pb[ni].w);
                }
            }
        }
        // epilogue: row = mi*16 + g + 8rh = k*16 + b ; register-local weighted 5:1 reduce
        float hb[2][4];
        #pragma unroll
        for (int rh = 0; rh < 2; rh++)
            #pragma unroll
            for (int cc = 0; cc < 4; cc++) hb[rh][cc] = 0.0f;
        #pragma unroll
        for (int mi = 0; mi < 5; mi++) {
            #pragma unroll
            for (int rh = 0; rh < 2; rh++) {
                float wk = wgt_s[mi * 16 + g + 8 * rh];
                #pragma unroll
                for (int ni = 0; ni < 2; ni++) {
                    #pragma unroll
                    for (int c = 0; c < 2; c++) {
                        int col = nb + ni * 8 + 2 * t + c;
                        hb[rh][ni * 2 + c] += wk * gelu_exact(acc[mi][ni][rh * 2 + c] + biasV[half * 128 + col]);
                    }
                }
            }
        }
        #pragma unroll
        for (int rh = 0; rh < 2; rh++) {
            int b = g + 8 * rh;
            #pragma unroll
            for (int ni = 0; ni < 2; ni++)
                #pragma unroll
                for (int c = 0; c < 2; c++) {
                    int col = nb + ni * 8 + 2 * t + c;
                    hbar_s[b * HLD + half * 128 + kperm16(col)] = __uint_as_float(f2tf(hb[rh][ni * 2 + c]));
                }
        }
    }
    __syncthreads();

    // ---------- phase 6: output GEMM (16 x 256) @ (256 x 256) ----------
    {
        const int nb2 = warp * 32;
        float acc[4][4];
        #pragma unroll
        for (int ni = 0; ni < 4; ni++)
            #pragma unroll
            for (int q = 0; q < 4; q++) acc[ni][q] = 0.0f;

        #pragma unroll 2
        for (int ks = 0; ks < 16; ks++) {
            int kb = ks * 16;
            const uint32* abase = hbU + g * HLD + kb + 4 * t;
            uint4 a0 = *(const uint4*)abase;
            uint4 a1 = *(const uint4*)(abase + 8 * HLD);
            #pragma unroll
            for (int ni = 0; ni < 4; ni++) {
                uint4 pb = __ldg(w24 + (nb2 + ni * 8 + g) * 64 + ks * 4 + t);
                mma_tf32(acc[ni], a0.x, a1.x, a0.y, a1.y, pb.x, pb.y);
                mma_tf32(acc[ni], a0.z, a1.z, a0.w, a1.w, pb.z, pb.w);
            }
        }

        #pragma unroll
        for (int rh = 0; rh < 2; rh++) {
            int b = g + 8 * rh;
            int av = anyv_s[b];
            int row = b0 + b;
            #pragma unroll
            for (int ni = 0; ni < 4; ni++) {
                int colb = nb2 + ni * 8 + 2 * t;
                float x0 = acc[ni][rh * 2 + 0];
                float x1 = acc[ni][rh * 2 + 1];
                float2 o;
                if (av) { o.x = x0 + b2s[colb]; o.y = x1 + b2s[colb + 1]; }
                else    { o.x = fbs[colb];      o.y = fbs[colb + 1]; }
                *(float2*)(out + (size_t)row * HID + colb) = o;
            }
        }
    }
}

// ---------------- launch ----------------
extern "C" void kernel_launch(void* const* d_in, const int* in_sizes, int n_in,
                              void* d_out, int out_size)
{
    const int*   res_idx   = (const int*)d_in[0];
    const int*   ss_idx    = (const int*)d_in[1];
    const float* dist      = (const float*)d_in[2];
    const int*   seq_sep   = (const int*)d_in[3];
    const float* angles    = (const float*)d_in[4];
    const void*  validp    = d_in[5];
    const float* res_table = (const float*)d_in[6];
    const float* ss_table  = (const float*)d_in[7];
    const float* cont_W    = (const float*)d_in[8];
    const float* cont_b    = (const float*)d_in[9];
    const float* attn_W1   = (const float*)d_in[10];
    const float* attn_b1   = (const float*)d_in[11];
    const float* attn_W2   = (const float*)d_in[12];
    const float* attn_b2   = (const float*)d_in[13];
    const float* val_W1    = (const float*)d_in[14];
    const float* val_b1    = (const float*)d_in[15];
    const float* val_W2    = (const float*)d_in[16];
    const float* val_b2    = (const float*)d_in[17];
    const float* fallback  = (const float*)d_in[18];
    float* out = (float*)d_out;

    cudaFuncSetAttribute(fused_all, cudaFuncAttributeMaxDynamicSharedMemorySize, SMEM_BYTES);

    reset_flags<<<1, 1>>>();
    detect_valid<<<148, 1024>>>((const unsigned int*)validp, (B_TOTAL * KNB) / 4);
    prep_weights<<<148, 256>>>(attn_W1, val_W1, val_W2);

    fused_all<<<B_TOTAL / TILE_B, 256, SMEM_BYTES>>>(
        res_idx, ss_idx, dist, seq_sep, angles, validp,
        res_table, ss_table, cont_W, cont_b,
        attn_b1, attn_W2, attn_b2, val_b1, val_b2, fallback, out);
}

// round 10
// speedup vs baseline: 2.6900x; 1.6790x over previous
#include <cuda_runtime.h>
#include <math.h>

#define B_TOTAL 131072
#define KNB 5
#define TILE_B 16
#define ROWSF (TILE_B * KNB)   // 80
#define COMB 128
#define HID 256
#define AH 128
#define HLD 272                // hbar stride (16 mod 32 -> conflict-free LDS.128 phases)
#define NRES 21
#define NSS 9

typedef unsigned int uint32;

// ---------------- device globals ----------------
__device__ float g_R1a[NRES * AH];    // res_table@W1a + b1a + cont_b fold
__device__ float g_S1a[NSS * AH];
__device__ float g_C1a[6 * AH];       // cont_W@W1a[96:128]
__device__ float g_R1v[NRES * HID];
__device__ float g_S1v[NSS * HID];
__device__ float g_C1v[6 * HID];
__device__ uint32 g_w2T[HID * HID];   // val_W2^T tf32, k16-permuted
__device__ int g_flag_u8, g_flag_f32;

// ---------------- helpers ----------------
__device__ __forceinline__ uint32 f2tf(float f) {
    uint32 r; asm("cvt.rna.tf32.f32 %0, %1;" : "=r"(r) : "f"(f)); return r;
}
__device__ __forceinline__ void mma_tf32(float d[4], uint32 a0, uint32 a1, uint32 a2, uint32 a3,
                                         uint32 b0, uint32 b1) {
    asm("mma.sync.aligned.m16n8k8.row.col.f32.tf32.tf32.f32 "
        "{%0,%1,%2,%3}, {%4,%5,%6,%7}, {%8,%9}, {%0,%1,%2,%3};"
        : "+f"(d[0]), "+f"(d[1]), "+f"(d[2]), "+f"(d[3])
        : "r"(a0), "r"(a1), "r"(a2), "r"(a3), "r"(b0), "r"(b1));
}
__device__ __forceinline__ float gelu_exact(float x) {
    return 0.5f * x * (1.0f + erff(x * 0.70710678118654752f));
}
// 16-wide k permutation: k = c*8 + h*4 + t  ->  slot = 4t + 2c + h
__device__ __forceinline__ int kperm16(int k) {
    return (k & ~15) | ((k & 3) << 2) | ((k & 8) >> 2) | ((k & 4) >> 2);
}

// ---------------- prep: factor tables + W2 transpose ----------------
__global__ void prep_tables(const float* __restrict__ attn_W1,
                            const float* __restrict__ attn_b1,
                            const float* __restrict__ val_W1,
                            const float* __restrict__ val_b1,
                            const float* __restrict__ val_W2,
                            const float* __restrict__ res_table,
                            const float* __restrict__ ss_table,
                            const float* __restrict__ cont_W,
                            const float* __restrict__ cont_b) {
    int tid = blockIdx.x * blockDim.x + threadIdx.x;
    int stride = gridDim.x * blockDim.x;
    for (int i = tid; i < NRES * AH; i += stride) {
        int r = i / AH, n = i % AH;
        float s = attn_b1[n];
        for (int c = 0; c < 64; c++) s += res_table[r * 64 + c] * attn_W1[c * AH + n];
        for (int c = 0; c < 32; c++) s += cont_b[c] * attn_W1[(96 + c) * AH + n];
        g_R1a[i] = s;
    }
    for (int i = tid; i < NSS * AH; i += stride) {
        int r = i / AH, n = i % AH;
        float s = 0.0f;
        for (int c = 0; c < 32; c++) s += ss_table[r * 32 + c] * attn_W1[(64 + c) * AH + n];
        g_S1a[i] = s;
    }
    for (int i = tid; i < 6 * AH; i += stride) {
        int j = i / AH, n = i % AH;
        float s = 0.0f;
        for (int c = 0; c < 32; c++) s += cont_W[j * 32 + c] * attn_W1[(96 + c) * AH + n];
        g_C1a[i] = s;
    }
    for (int i = tid; i < NRES * HID; i += stride) {
        int r = i / HID, n = i % HID;
        float s = val_b1[n];
        for (int c = 0; c < 64; c++) s += res_table[r * 64 + c] * val_W1[c * HID + n];
        for (int c = 0; c < 32; c++) s += cont_b[c] * val_W1[(96 + c) * HID + n];
        g_R1v[i] = s;
    }
    for (int i = tid; i < NSS * HID; i += stride) {
        int r = i / HID, n = i % HID;
        float s = 0.0f;
        for (int c = 0; c < 32; c++) s += ss_table[r * 32 + c] * val_W1[(64 + c) * HID + n];
        g_S1v[i] = s;
    }
    for (int i = tid; i < 6 * HID; i += stride) {
        int j = i / HID, n = i % HID;
        float s = 0.0f;
        for (int c = 0; c < 32; c++) s += cont_W[j * 32 + c] * val_W1[(96 + c) * HID + n];
        g_C1v[i] = s;
    }
    for (int i = tid; i < HID * HID; i += stride) {
        int n = i >> 8, k = i & 255;
        g_w2T[(n << 8) + kperm16(k)] = f2tf(val_W2[k * HID + n]);
    }
}

// ---------------- valid-dtype probe ----------------
__global__ void reset_flags() { g_flag_u8 = 0; g_flag_f32 = 0; }

__global__ void detect_valid(const unsigned int* __restrict__ v, int n) {
    int f8 = 0, f32 = 0;
    for (int i = blockIdx.x * blockDim.x + threadIdx.x; i < n; i += gridDim.x * blockDim.x) {
        unsigned int w = v[i];
        if (w == 0x3F800000u) f32 = 1;
        else if (w > 1u) f8 = 1;
    }
    if (__syncthreads_or(f8) && threadIdx.x == 0) atomicOr(&g_flag_u8, 1);
    if (__syncthreads_or(f32) && threadIdx.x == 0) atomicOr(&g_flag_f32, 1);
}

// ---------------- fused kernel smem (floats) ----------------
// feat @0: 480 | score @480: 80 | wgt @560: 80 | hbar @640: 16*272=4352
// b2s @4992: 256 | fbs @5248: 256 | ridx @5504: 80 | sidx @5584: 80 | anyv @5664: 16
// total 5680 floats = 22720 B
#define SMEM_BYTES 22720

__global__ void __launch_bounds__(256, 4) fused_all(
    const int* __restrict__ res_idx,
    const int* __restrict__ ss_idx,
    const float* __restrict__ dist,
    const int* __restrict__ seq_sep,
    const float* __restrict__ angles,
    const void* __restrict__ validp,
    const float* __restrict__ attn_W2,
    const float* __restrict__ attn_b2,
    const float* __restrict__ val_b2,
    const float* __restrict__ fallback,
    float* __restrict__ out)
{
    extern __shared__ float sm[];
    float* feat    = sm;
    float* score_s = sm + 480;
    float* wgt_s   = sm + 560;
    float* hbar_s  = sm + 640;
    float* b2s     = sm + 4992;
    float* fbs     = sm + 5248;
    int*   ridx    = (int*)(sm + 5504);
    int*   sidx    = (int*)(sm + 5584);
    int*   anyv_s  = (int*)(sm + 5664);

    const int tid  = threadIdx.x;
    const int lane = tid & 31;
    const int warp = tid >> 5;      // 0..7
    const int g    = lane >> 2;     // 0..7
    const int t    = lane & 3;      // 0..3
    const int b0   = blockIdx.x * TILE_B;
    const int gr0  = b0 * KNB;

    const float4* R1a4 = (const float4*)g_R1a;   // 32 f4 per row
    const float4* S1a4 = (const float4*)g_S1a;
    const float4* C1a4 = (const float4*)g_C1a;
    const float4* R1v4 = (const float4*)g_R1v;   // 64 f4 per row
    const float4* S1v4 = (const float4*)g_S1v;
    const float4* C1v4 = (const float4*)g_C1v;
    const uint32* hbU  = (const uint32*)hbar_s;
    const uint4*  w24  = (const uint4*)g_w2T;    // 64 uint4 per row

    // ---------- phase 0: constants + features (natural row order j = b*5+k) ----------
    if (tid < HID) { b2s[tid] = val_b2[tid]; fbs[tid] = fallback[tid]; }
    if (tid < ROWSF) {
        int gr = gr0 + tid;
        ridx[tid] = res_idx[gr];
        sidx[tid] = ss_idx[gr];
        float d = dist[gr];
        if (d != d) d = 0.0f;
        feat[tid * 6 + 0] = d * (1.0f / 15.0f);
        feat[tid * 6 + 1] = log1pf(fabsf((float)seq_sep[gr])) * 0.2f;
        float4 a = ((const float4*)angles)[gr];
        feat[tid * 6 + 2] = (a.x != a.x) ? 0.0f : a.x;
        feat[tid * 6 + 3] = (a.y != a.y) ? 0.0f : a.y;
        feat[tid * 6 + 4] = (a.z != a.z) ? 0.0f : a.z;
        feat[tid * 6 + 5] = (a.w != a.w) ? 0.0f : a.w;
    }
    __syncthreads();

    // ---------- phase 1: attention scores via factored tables ----------
    // warp handles rows warp*10 .. warp*10+9 ; lane handles col quad = lane (128 cols)
    {
        float4 c1[6];
        #pragma unroll
        for (int j = 0; j < 6; j++) c1[j] = __ldg(C1a4 + j * 32 + lane);
        float4 w2q = __ldg(((const float4*)attn_W2) + lane);
        #pragma unroll 2
        for (int i = 0; i < 10; i++) {
            int j = warp * 10 + i;
            int r = ridx[j], s = sidx[j];
            float4 p = __ldg(R1a4 + r * 32 + lane);
            float4 sv = __ldg(S1a4 + s * 32 + lane);
            p.x += sv.x; p.y += sv.y; p.z += sv.z; p.w += sv.w;
            const float* fj = feat + j * 6;
            #pragma unroll
            for (int jj = 0; jj < 6; jj++) {
                float f = fj[jj];
                p.x += f * c1[jj].x; p.y += f * c1[jj].y;
                p.z += f * c1[jj].z; p.w += f * c1[jj].w;
            }
            float part = gelu_exact(p.x) * w2q.x + gelu_exact(p.y) * w2q.y
                       + gelu_exact(p.z) * w2q.z + gelu_exact(p.w) * w2q.w;
            #pragma unroll
            for (int off = 16; off; off >>= 1)
                part += __shfl_xor_sync(0xFFFFFFFFu, part, off);
            if (lane == 0) score_s[j] = part;
        }
    }
    __syncthreads();

    // ---------- phase 2: softmax + validity (tid<16) ----------
    if (tid < TILE_B) {
        int gb = b0 + tid;
        float ab2 = attn_b2[0];
        int fu8 = g_flag_u8, ff32 = g_flag_f32;
        float s[KNB];
        int any = 0;
        #pragma unroll
        for (int k = 0; k < KNB; k++) {
            int idx = gb * KNB + k;
            int v;
            if (ff32)      v = (((const float*)validp)[idx] != 0.0f);
            else if (fu8)  v = (((const unsigned char*)validp)[idx] != 0);
            else           v = (((const int*)validp)[idx] != 0);
            any |= v;
            s[k] = v ? (score_s[tid * KNB + k] + ab2) : -10000.0f;
        }
        float m = s[0];
        #pragma unroll
        for (int k = 1; k < KNB; k++) m = fmaxf(m, s[k]);
        float e[KNB], sum = 0.0f;
        #pragma unroll
        for (int k = 0; k < KNB; k++) { e[k] = expf(s[k] - m); sum += e[k]; }
        float inv = 1.0f / sum;
        #pragma unroll
        for (int k = 0; k < KNB; k++) wgt_s[tid * KNB + k] = e[k] * inv;
        anyv_s[tid] = any;
    }
    __syncthreads();

    // ---------- phase 3: value path -> hbar (fp32, factored tables) ----------
    // item = (b, col-quad q of 64); 16*64 = 1024 items, 4 per thread.
    // 64 consecutive threads share b -> wgt==0 branch is warp-uniform.
    #pragma unroll 1
    for (int it = tid; it < TILE_B * 64; it += 256) {
        int b = it >> 6, q = it & 63;
        float4 c1[6];
        #pragma unroll
        for (int j = 0; j < 6; j++) c1[j] = __ldg(C1v4 + j * 64 + q);
        float ax = 0.0f, ay = 0.0f, az = 0.0f, aw = 0.0f;
        #pragma unroll
        for (int k = 0; k < KNB; k++) {
            int j = b * KNB + k;
            float wk = wgt_s[j];
            if (wk != 0.0f) {
                int r = ridx[j], s = sidx[j];
                float4 p = __ldg(R1v4 + r * 64 + q);
                float4 sv = __ldg(S1v4 + s * 64 + q);
                p.x += sv.x; p.y += sv.y; p.z += sv.z; p.w += sv.w;
                const float* fj = feat + j * 6;
                #pragma unroll
                for (int jj = 0; jj < 6; jj++) {
                    float f = fj[jj];
                    p.x += f * c1[jj].x; p.y += f * c1[jj].y;
                    p.z += f * c1[jj].z; p.w += f * c1[jj].w;
                }
                ax += wk * gelu_exact(p.x);
                ay += wk * gelu_exact(p.y);
                az += wk * gelu_exact(p.z);
                aw += wk * gelu_exact(p.w);
            }
        }
        int col = q * 4;
        float* hb = hbar_s + b * HLD;
        hb[kperm16(col)]     = __uint_as_float(f2tf(ax));
        hb[kperm16(col + 1)] = __uint_as_float(f2tf(ay));
        hb[kperm16(col + 2)] = __uint_as_float(f2tf(az));
        hb[kperm16(col + 3)] = __uint_as_float(f2tf(aw));
    }
    __syncthreads();

    // ---------- phase 4: output GEMM (16 x 256) @ (256 x 256), tensor cores ----------
    {
        const int nb2 = warp * 32;
        float acc[4][4];
        #pragma unroll
        for (int ni = 0; ni < 4; ni++)
            #pragma unroll
            for (int q = 0; q < 4; q++) acc[ni][q] = 0.0f;

        #pragma unroll 2
        for (int ks = 0; ks < 16; ks++) {
            int kb = ks * 16;
            const uint32* abase = hbU + g * HLD + kb + 4 * t;
            uint4 a0 = *(const uint4*)abase;
            uint4 a1 = *(const uint4*)(abase + 8 * HLD);
            #pragma unroll
            for (int ni = 0; ni < 4; ni++) {
                uint4 pb = __ldg(w24 + (nb2 + ni * 8 + g) * 64 + ks * 4 + t);
                mma_tf32(acc[ni], a0.x, a1.x, a0.y, a1.y, pb.x, pb.y);
                mma_tf32(acc[ni], a0.z, a1.z, a0.w, a1.w, pb.z, pb.w);
            }
        }

        #pragma unroll
        for (int rh = 0; rh < 2; rh++) {
            int b = g + 8 * rh;
            int av = anyv_s[b];
            int row = b0 + b;
            #pragma unroll
            for (int ni = 0; ni < 4; ni++) {
                int colb = nb2 + ni * 8 + 2 * t;
                float x0 = acc[ni][rh * 2 + 0];
                float x1 = acc[ni][rh * 2 + 1];
                float2 o;
                if (av) { o.x = x0 + b2s[colb]; o.y = x1 + b2s[colb + 1]; }
                else    { o.x = fbs[colb];      o.y = fbs[colb + 1]; }
                *(float2*)(out + (size_t)row * HID + colb) = o;
            }
        }
    }
}

// ---------------- launch ----------------
extern "C" void kernel_launch(void* const* d_in, const int* in_sizes, int n_in,
                              void* d_out, int out_size)
{
    const int*   res_idx   = (const int*)d_in[0];
    const int*   ss_idx    = (const int*)d_in[1];
    const float* dist      = (const float*)d_in[2];
    const int*   seq_sep   = (const int*)d_in[3];
    const float* angles    = (const float*)d_in[4];
    const void*  validp    = d_in[5];
    const float* res_table = (const float*)d_in[6];
    const float* ss_table  = (const float*)d_in[7];
    const float* cont_W    = (const float*)d_in[8];
    const float* cont_b    = (const float*)d_in[9];
    const float* attn_W1   = (const float*)d_in[10];
    const float* attn_b1   = (const float*)d_in[11];
    const float* attn_W2   = (const float*)d_in[12];
    const float* attn_b2   = (const float*)d_in[13];
    const float* val_W1    = (const float*)d_in[14];
    const float* val_b1    = (const float*)d_in[15];
    const float* val_W2    = (const float*)d_in[16];
    const float* val_b2    = (const float*)d_in[17];
    const float* fallback  = (const float*)d_in[18];
    float* out = (float*)d_out;

    reset_flags<<<1, 1>>>();
    detect_valid<<<148, 1024>>>((const unsigned int*)validp, (B_TOTAL * KNB) / 4);
    prep_tables<<<148, 256>>>(attn_W1, attn_b1, val_W1, val_b1, val_W2,
                              res_table, ss_table, cont_W, cont_b);

    fused_all<<<B_TOTAL / TILE_B, 256, SMEM_BYTES>>>(
        res_idx, ss_idx, dist, seq_sep, angles, validp,
        attn_W2, attn_b2, val_b2, fallback, out);
}

// round 12
// speedup vs baseline: 3.3838x; 1.2579x over previous
#include <cuda_runtime.h>
#include <math.h>

#define B_TOTAL 131072
#define KNB 5
#define TILE_B 16
#define ROWSF (TILE_B * KNB)   // 80
#define COMB 128
#define HID 256
#define AH 128
#define HLD 272                // hbar stride (16 mod 32 -> conflict-free LDS.128 phases)
#define NRES 21
#define NSS 9

typedef unsigned int uint32;

// ---------------- device globals ----------------
__device__ float g_R1a[NRES * AH];    // res_table@W1a + b1a + cont_b fold
__device__ float g_S1a[NSS * AH];
__device__ float g_C1a[6 * AH];       // cont_W@W1a[96:128]
__device__ float g_R1v[NRES * HID];
__device__ float g_S1v[NSS * HID];
__device__ float g_C1v[6 * HID];
__device__ uint32 g_w2T[HID * HID];   // val_W2^T tf32, k16-permuted
__device__ int g_flag_u8, g_flag_f32;

// ---------------- helpers ----------------
__device__ __forceinline__ uint32 f2tf(float f) {
    uint32 r; asm("cvt.rna.tf32.f32 %0, %1;" : "=r"(r) : "f"(f)); return r;
}
__device__ __forceinline__ void mma_tf32(float d[4], uint32 a0, uint32 a1, uint32 a2, uint32 a3,
                                         uint32 b0, uint32 b1) {
    asm("mma.sync.aligned.m16n8k8.row.col.f32.tf32.tf32.f32 "
        "{%0,%1,%2,%3}, {%4,%5,%6,%7}, {%8,%9}, {%0,%1,%2,%3};"
        : "+f"(d[0]), "+f"(d[1]), "+f"(d[2]), "+f"(d[3])
        : "r"(a0), "r"(a1), "r"(a2), "r"(a3), "r"(b0), "r"(b1));
}
// fast GELU: 0.5x(1+tanh(0.79788456(x + 0.044715 x^3))) via MUFU.TANH (6 instrs)
__device__ __forceinline__ float gelu_fast(float x) {
    float s = x * x;
    float t = fmaf(s, 0.0356774081f, 0.7978845608f);
    float u = x * t;
    float th;
    asm("tanh.approx.f32 %0, %1;" : "=f"(th) : "f"(u));
    float h = 0.5f * x;
    return fmaf(h, th, h);
}
// 16-wide k permutation: k = c*8 + h*4 + t  ->  slot = 4t + 2c + h
__device__ __forceinline__ int kperm16(int k) {
    return (k & ~15) | ((k & 3) << 2) | ((k & 8) >> 2) | ((k & 4) >> 2);
}

// ---------------- prep: factor tables + W2 transpose ----------------
__global__ void prep_tables(const float* __restrict__ attn_W1,
                            const float* __restrict__ attn_b1,
                            const float* __restrict__ val_W1,
                            const float* __restrict__ val_b1,
                            const float* __restrict__ val_W2,
                            const float* __restrict__ res_table,
                            const float* __restrict__ ss_table,
                            const float* __restrict__ cont_W,
                            const float* __restrict__ cont_b) {
    int tid = blockIdx.x * blockDim.x + threadIdx.x;
    int stride = gridDim.x * blockDim.x;
    for (int i = tid; i < NRES * AH; i += stride) {
        int r = i / AH, n = i % AH;
        float s = attn_b1[n];
        for (int c = 0; c < 64; c++) s += res_table[r * 64 + c] * attn_W1[c * AH + n];
        for (int c = 0; c < 32; c++) s += cont_b[c] * attn_W1[(96 + c) * AH + n];
        g_R1a[i] = s;
    }
    for (int i = tid; i < NSS * AH; i += stride) {
        int r = i / AH, n = i % AH;
        float s = 0.0f;
        for (int c = 0; c < 32; c++) s += ss_table[r * 32 + c] * attn_W1[(64 + c) * AH + n];
        g_S1a[i] = s;
    }
    for (int i = tid; i < 6 * AH; i += stride) {
        int j = i / AH, n = i % AH;
        float s = 0.0f;
        for (int c = 0; c < 32; c++) s += cont_W[j * 32 + c] * attn_W1[(96 + c) * AH + n];
        g_C1a[i] = s;
    }
    for (int i = tid; i < NRES * HID; i += stride) {
        int r = i / HID, n = i % HID;
        float s = val_b1[n];
        for (int c = 0; c < 64; c++) s += res_table[r * 64 + c] * val_W1[c * HID + n];
        for (int c = 0; c < 32; c++) s += cont_b[c] * val_W1[(96 + c) * HID + n];
        g_R1v[i] = s;
    }
    for (int i = tid; i < NSS * HID; i += stride) {
        int r = i / HID, n = i % HID;
        float s = 0.0f;
        for (int c = 0; c < 32; c++) s += ss_table[r * 32 + c] * val_W1[(64 + c) * HID + n];
        g_S1v[i] = s;
    }
    for (int i = tid; i < 6 * HID; i += stride) {
        int j = i / HID, n = i % HID;
        float s = 0.0f;
        for (int c = 0; c < 32; c++) s += cont_W[j * 32 + c] * val_W1[(96 + c) * HID + n];
        g_C1v[i] = s;
    }
    for (int i = tid; i < HID * HID; i += stride) {
        int n = i >> 8, k = i & 255;
        g_w2T[(n << 8) + kperm16(k)] = f2tf(val_W2[k * HID + n]);
    }
}

// ---------------- valid-dtype probe ----------------
__global__ void reset_flags() { g_flag_u8 = 0; g_flag_f32 = 0; }

__global__ void detect_valid(const unsigned int* __restrict__ v, int n) {
    int f8 = 0, f32 = 0;
    for (int i = blockIdx.x * blockDim.x + threadIdx.x; i < n; i += gridDim.x * blockDim.x) {
        unsigned int w = v[i];
        if (w == 0x3F800000u) f32 = 1;
        else if (w > 1u) f8 = 1;
    }
    if (__syncthreads_or(f8) && threadIdx.x == 0) atomicOr(&g_flag_u8, 1);
    if (__syncthreads_or(f32) && threadIdx.x == 0) atomicOr(&g_flag_f32, 1);
}

// ---------------- fused kernel smem (floats) ----------------
// feat @0: 480 | score @480: 80 | wgt @560: 80 | hbar @640: 16*272=4352
// b2s @4992: 256 | fbs @5248: 256 | ridx @5504: 80 | sidx @5584: 80 | anyv @5664: 16
// total 5680 floats = 22720 B
#define SMEM_BYTES 22720

__global__ void __launch_bounds__(256, 4) fused_all(
    const int* __restrict__ res_idx,
    const int* __restrict__ ss_idx,
    const float* __restrict__ dist,
    const int* __restrict__ seq_sep,
    const float* __restrict__ angles,
    const void* __restrict__ validp,
    const float* __restrict__ attn_W2,
    const float* __restrict__ attn_b2,
    const float* __restrict__ val_b2,
    const float* __restrict__ fallback,
    float* __restrict__ out)
{
    extern __shared__ float sm[];
    float* feat    = sm;
    float* score_s = sm + 480;
    float* wgt_s   = sm + 560;
    float* hbar_s  = sm + 640;
    float* b2s     = sm + 4992;
    float* fbs     = sm + 5248;
    int*   ridx    = (int*)(sm + 5504);
    int*   sidx    = (int*)(sm + 5584);
    int*   anyv_s  = (int*)(sm + 5664);

    const int tid  = threadIdx.x;
    const int lane = tid & 31;
    const int warp = tid >> 5;      // 0..7
    const int g    = lane >> 2;     // 0..7
    const int t    = lane & 3;      // 0..3
    const int b0   = blockIdx.x * TILE_B;
    const int gr0  = b0 * KNB;

    const float4* R1a4 = (const float4*)g_R1a;   // 32 f4 per row
    const float4* S1a4 = (const float4*)g_S1a;
    const float4* C1a4 = (const float4*)g_C1a;
    const float4* R1v4 = (const float4*)g_R1v;   // 64 f4 per row
    const float4* S1v4 = (const float4*)g_S1v;
    const float4* C1v4 = (const float4*)g_C1v;
    const uint32* hbU  = (const uint32*)hbar_s;
    const uint4*  w24  = (const uint4*)g_w2T;    // 64 uint4 per row

    // ---------- phase 0: constants + features (natural row order j = b*5+k) ----------
    if (tid < HID) { b2s[tid] = val_b2[tid]; fbs[tid] = fallback[tid]; }
    if (tid < ROWSF) {
        int gr = gr0 + tid;
        ridx[tid] = res_idx[gr];
        sidx[tid] = ss_idx[gr];
        float d = dist[gr];
        if (d != d) d = 0.0f;
        feat[tid * 6 + 0] = d * (1.0f / 15.0f);
        feat[tid * 6 + 1] = log1pf(fabsf((float)seq_sep[gr])) * 0.2f;
        float4 a = ((const float4*)angles)[gr];
        feat[tid * 6 + 2] = (a.x != a.x) ? 0.0f : a.x;
        feat[tid * 6 + 3] = (a.y != a.y) ? 0.0f : a.y;
        feat[tid * 6 + 4] = (a.z != a.z) ? 0.0f : a.z;
        feat[tid * 6 + 5] = (a.w != a.w) ? 0.0f : a.w;
    }
    __syncthreads();

    // ---------- phase 1: attention scores via factored tables ----------
    // warp handles rows warp*10 .. warp*10+9 ; lane handles col quad = lane (128 cols)
    {
        float4 c1[6];
        #pragma unroll
        for (int j = 0; j < 6; j++) c1[j] = __ldg(C1a4 + j * 32 + lane);
        float4 w2q = __ldg(((const float4*)attn_W2) + lane);
        #pragma unroll 2
        for (int i = 0; i < 10; i++) {
            int j = warp * 10 + i;
            int r = ridx[j], s = sidx[j];
            float4 p = __ldg(R1a4 + r * 32 + lane);
            float4 sv = __ldg(S1a4 + s * 32 + lane);
            p.x += sv.x; p.y += sv.y; p.z += sv.z; p.w += sv.w;
            const float* fj = feat + j * 6;
            #pragma unroll
            for (int jj = 0; jj < 6; jj++) {
                float f = fj[jj];
                p.x += f * c1[jj].x; p.y += f * c1[jj].y;
                p.z += f * c1[jj].z; p.w += f * c1[jj].w;
            }
            float part = gelu_fast(p.x) * w2q.x + gelu_fast(p.y) * w2q.y
                       + gelu_fast(p.z) * w2q.z + gelu_fast(p.w) * w2q.w;
            #pragma unroll
            for (int off = 16; off; off >>= 1)
                part += __shfl_xor_sync(0xFFFFFFFFu, part, off);
            if (lane == 0) score_s[j] = part;
        }
    }
    __syncthreads();

    // ---------- phase 2: softmax + validity (tid<16) ----------
    if (tid < TILE_B) {
        int gb = b0 + tid;
        float ab2 = attn_b2[0];
        int fu8 = g_flag_u8, ff32 = g_flag_f32;
        float s[KNB];
        int any = 0;
        #pragma unroll
        for (int k = 0; k < KNB; k++) {
            int idx = gb * KNB + k;
            int v;
            if (ff32)      v = (((const float*)validp)[idx] != 0.0f);
            else if (fu8)  v = (((const unsigned char*)validp)[idx] != 0);
            else           v = (((const int*)validp)[idx] != 0);
            any |= v;
            s[k] = v ? (score_s[tid * KNB + k] + ab2) : -10000.0f;
        }
        float m = s[0];
        #pragma unroll
        for (int k = 1; k < KNB; k++) m = fmaxf(m, s[k]);
        float e[KNB], sum = 0.0f;
        #pragma unroll
        for (int k = 0; k < KNB; k++) { e[k] = expf(s[k] - m); sum += e[k]; }
        float inv = 1.0f / sum;
        #pragma unroll
        for (int k = 0; k < KNB; k++) wgt_s[tid * KNB + k] = e[k] * inv;
        anyv_s[tid] = any;
    }
    __syncthreads();

    // ---------- phase 3: value path -> hbar (fp32, factored tables) ----------
    // item = (b, col-quad q of 64); 16*64 = 1024 items, 4 per thread.
    // 64 consecutive threads share b -> wgt==0 branch is warp-uniform.
    #pragma unroll 1
    for (int it = tid; it < TILE_B * 64; it += 256) {
        int b = it >> 6, q = it & 63;
        float4 c1[6];
        #pragma unroll
        for (int j = 0; j < 6; j++) c1[j] = __ldg(C1v4 + j * 64 + q);
        float ax = 0.0f, ay = 0.0f, az = 0.0f, aw = 0.0f;
        #pragma unroll
        for (int k = 0; k < KNB; k++) {
            int j = b * KNB + k;
            float wk = wgt_s[j];
            if (wk != 0.0f) {
                int r = ridx[j], s = sidx[j];
                float4 p = __ldg(R1v4 + r * 64 + q);
                float4 sv = __ldg(S1v4 + s * 64 + q);
                p.x += sv.x; p.y += sv.y; p.z += sv.z; p.w += sv.w;
                const float* fj = feat + j * 6;
                #pragma unroll
                for (int jj = 0; jj < 6; jj++) {
                    float f = fj[jj];
                    p.x += f * c1[jj].x; p.y += f * c1[jj].y;
                    p.z += f * c1[jj].z; p.w += f * c1[jj].w;
                }
                ax += wk * gelu_fast(p.x);
                ay += wk * gelu_fast(p.y);
                az += wk * gelu_fast(p.z);
                aw += wk * gelu_fast(p.w);
            }
        }
        int col = q * 4;
        float* hb = hbar_s + b * HLD;
        hb[kperm16(col)]     = __uint_as_float(f2tf(ax));
        hb[kperm16(col + 1)] = __uint_as_float(f2tf(ay));
        hb[kperm16(col + 2)] = __uint_as_float(f2tf(az));
        hb[kperm16(col + 3)] = __uint_as_float(f2tf(aw));
    }
    __syncthreads();

    // ---------- phase 4: output GEMM (16 x 256) @ (256 x 256), tensor cores ----------
    {
        const int nb2 = warp * 32;
        float acc[4][4];
        #pragma unroll
        for (int ni = 0; ni < 4; ni++)
            #pragma unroll
            for (int q = 0; q < 4; q++) acc[ni][q] = 0.0f;

        #pragma unroll 2
        for (int ks = 0; ks < 16; ks++) {
            int kb = ks * 16;
            const uint32* abase = hbU + g * HLD + kb + 4 * t;
            uint4 a0 = *(const uint4*)abase;
            uint4 a1 = *(const uint4*)(abase + 8 * HLD);
            #pragma unroll
            for (int ni = 0; ni < 4; ni++) {
                uint4 pb = __ldg(w24 + (nb2 + ni * 8 + g) * 64 + ks * 4 + t);
                mma_tf32(acc[ni], a0.x, a1.x, a0.y, a1.y, pb.x, pb.y);
                mma_tf32(acc[ni], a0.z, a1.z, a0.w, a1.w, pb.z, pb.w);
            }
        }

        #pragma unroll
        for (int rh = 0; rh < 2; rh++) {
            int b = g + 8 * rh;
            int av = anyv_s[b];
            int row = b0 + b;
            #pragma unroll
            for (int ni = 0; ni < 4; ni++) {
                int colb = nb2 + ni * 8 + 2 * t;
                float x0 = acc[ni][rh * 2 + 0];
                float x1 = acc[ni][rh * 2 + 1];
                float2 o;
                if (av) { o.x = x0 + b2s[colb]; o.y = x1 + b2s[colb + 1]; }
                else    { o.x = fbs[colb];      o.y = fbs[colb + 1]; }
                *(float2*)(out + (size_t)row * HID + colb) = o;
            }
        }
    }
}

// ---------------- launch ----------------
extern "C" void kernel_launch(void* const* d_in, const int* in_sizes, int n_in,
                              void* d_out, int out_size)
{
    const int*   res_idx   = (const int*)d_in[0];
    const int*   ss_idx    = (const int*)d_in[1];
    const float* dist      = (const float*)d_in[2];
    const int*   seq_sep   = (const int*)d_in[3];
    const float* angles    = (const float*)d_in[4];
    const void*  validp    = d_in[5];
    const float* res_table = (const float*)d_in[6];
    const float* ss_table  = (const float*)d_in[7];
    const float* cont_W    = (const float*)d_in[8];
    const float* cont_b    = (const float*)d_in[9];
    const float* attn_W1   = (const float*)d_in[10];
    const float* attn_b1   = (const float*)d_in[11];
    const float* attn_W2   = (const float*)d_in[12];
    const float* attn_b2   = (const float*)d_in[13];
    const float* val_W1    = (const float*)d_in[14];
    const float* val_b1    = (const float*)d_in[15];
    const float* val_W2    = (const float*)d_in[16];
    const float* val_b2    = (const float*)d_in[17];
    const float* fallback  = (const float*)d_in[18];
    float* out = (float*)d_out;

    reset_flags<<<1, 1>>>();
    detect_valid<<<148, 1024>>>((const unsigned int*)validp, (B_TOTAL * KNB) / 4);
    prep_tables<<<148, 256>>>(attn_W1, attn_b1, val_W1, val_b1, val_W2,
                              res_table, ss_table, cont_W, cont_b);

    fused_all<<<B_TOTAL / TILE_B, 256, SMEM_BYTES>>>(
        res_idx, ss_idx, dist, seq_sep, angles, validp,
        attn_W2, attn_b2, val_b2, fallback, out);
}

// round 14
// speedup vs baseline: 3.9697x; 1.1732x over previous
#include <cuda_runtime.h>
#include <math.h>

#define B_TOTAL 131072
#define KNB 5
#define TILE_B 32
#define ROWSF (TILE_B * KNB)   // 160
#define HID 256
#define AH 128
#define HLD 272                // hbar stride (16 mod 32 -> conflict-free LDS.128)
#define NRES 21
#define NSS 9
#define NRS (NRES * NSS)       // 189

typedef unsigned int uint32;

// ---------------- device globals ----------------
__device__ float g_R1a[NRES * AH];
__device__ float g_S1a[NSS * AH];
__device__ float g_C1a[6 * AH];
__device__ float g_R1v[NRES * HID];
__device__ float g_S1v[NSS * HID];
__device__ float g_C1v[6 * HID];
__device__ float g_RS1a[NRS * AH];    // fused res+ss attn table (97 KB)
__device__ float g_RS1v[NRS * HID];   // fused res+ss value table (194 KB)
__device__ uint32 g_w2T[HID * HID];   // val_W2^T tf32, k16-permuted
__device__ int g_flag_u8, g_flag_f32;

// ---------------- helpers ----------------
__device__ __forceinline__ uint32 f2tf(float f) {
    uint32 r; asm("cvt.rna.tf32.f32 %0, %1;" : "=r"(r) : "f"(f)); return r;
}
__device__ __forceinline__ void mma_tf32(float d[4], uint32 a0, uint32 a1, uint32 a2, uint32 a3,
                                         uint32 b0, uint32 b1) {
    asm("mma.sync.aligned.m16n8k8.row.col.f32.tf32.tf32.f32 "
        "{%0,%1,%2,%3}, {%4,%5,%6,%7}, {%8,%9}, {%0,%1,%2,%3};"
        : "+f"(d[0]), "+f"(d[1]), "+f"(d[2]), "+f"(d[3])
        : "r"(a0), "r"(a1), "r"(a2), "r"(a3), "r"(b0), "r"(b1));
}
// fast GELU via MUFU.TANH
__device__ __forceinline__ float gelu_fast(float x) {
    float s = x * x;
    float t = fmaf(s, 0.0356774081f, 0.7978845608f);
    float u = x * t;
    float th;
    asm("tanh.approx.f32 %0, %1;" : "=f"(th) : "f"(u));
    float h = 0.5f * x;
    return fmaf(h, th, h);
}
// 16-wide k permutation: k = c*8 + h*4 + t  ->  slot = 4t + 2c + h
__device__ __forceinline__ int kperm16(int k) {
    return (k & ~15) | ((k & 3) << 2) | ((k & 8) >> 2) | ((k & 4) >> 2);
}

// ---------------- prep 1: factor tables + W2 transpose ----------------
__global__ void prep_tables(const float* __restrict__ attn_W1,
                            const float* __restrict__ attn_b1,
                            const float* __restrict__ val_W1,
                            const float* __restrict__ val_b1,
                            const float* __restrict__ val_W2,
                            const float* __restrict__ res_table,
                            const float* __restrict__ ss_table,
                            const float* __restrict__ cont_W,
                            const float* __restrict__ cont_b) {
    int tid = blockIdx.x * blockDim.x + threadIdx.x;
    int stride = gridDim.x * blockDim.x;
    for (int i = tid; i < NRES * AH; i += stride) {
        int r = i / AH, n = i % AH;
        float s = attn_b1[n];
        for (int c = 0; c < 64; c++) s += res_table[r * 64 + c] * attn_W1[c * AH + n];
        for (int c = 0; c < 32; c++) s += cont_b[c] * attn_W1[(96 + c) * AH + n];
        g_R1a[i] = s;
    }
    for (int i = tid; i < NSS * AH; i += stride) {
        int r = i / AH, n = i % AH;
        float s = 0.0f;
        for (int c = 0; c < 32; c++) s += ss_table[r * 32 + c] * attn_W1[(64 + c) * AH + n];
        g_S1a[i] = s;
    }
    for (int i = tid; i < 6 * AH; i += stride) {
        int j = i / AH, n = i % AH;
        float s = 0.0f;
        for (int c = 0; c < 32; c++) s += cont_W[j * 32 + c] * attn_W1[(96 + c) * AH + n];
        g_C1a[i] = s;
    }
    for (int i = tid; i < NRES * HID; i += stride) {
        int r = i / HID, n = i % HID;
        float s = val_b1[n];
        for (int c = 0; c < 64; c++) s += res_table[r * 64 + c] * val_W1[c * HID + n];
        for (int c = 0; c < 32; c++) s += cont_b[c] * val_W1[(96 + c) * HID + n];
        g_R1v[i] = s;
    }
    for (int i = tid; i < NSS * HID; i += stride) {
        int r = i / HID, n = i % HID;
        float s = 0.0f;
        for (int c = 0; c < 32; c++) s += ss_table[r * 32 + c] * val_W1[(64 + c) * HID + n];
        g_S1v[i] = s;
    }
    for (int i = tid; i < 6 * HID; i += stride) {
        int j = i / HID, n = i % HID;
        float s = 0.0f;
        for (int c = 0; c < 32; c++) s += cont_W[j * 32 + c] * val_W1[(96 + c) * HID + n];
        g_C1v[i] = s;
    }
    for (int i = tid; i < HID * HID; i += stride) {
        int n = i >> 8, k = i & 255;
        g_w2T[(n << 8) + kperm16(k)] = f2tf(val_W2[k * HID + n]);
    }
}

// ---------------- prep 2: fuse res+ss tables ----------------
__global__ void prep_fuse() {
    int tid = blockIdx.x * blockDim.x + threadIdx.x;
    int stride = gridDim.x * blockDim.x;
    for (int i = tid; i < NRS * AH; i += stride) {
        int rs = i / AH, n = i % AH;
        g_RS1a[i] = g_R1a[(rs / NSS) * AH + n] + g_S1a[(rs % NSS) * AH + n];
    }
    for (int i = tid; i < NRS * HID; i += stride) {
        int rs = i / HID, n = i % HID;
        g_RS1v[i] = g_R1v[(rs / NSS) * HID + n] + g_S1v[(rs % NSS) * HID + n];
    }
}

// ---------------- valid-dtype probe ----------------
__global__ void reset_flags() { g_flag_u8 = 0; g_flag_f32 = 0; }

__global__ void detect_valid(const unsigned int* __restrict__ v, int n) {
    int f8 = 0, f32 = 0;
    for (int i = blockIdx.x * blockDim.x + threadIdx.x; i < n; i += gridDim.x * blockDim.x) {
        unsigned int w = v[i];
        if (w == 0x3F800000u) f32 = 1;
        else if (w > 1u) f8 = 1;
    }
    if (__syncthreads_or(f8) && threadIdx.x == 0) atomicOr(&g_flag_u8, 1);
    if (__syncthreads_or(f32) && threadIdx.x == 0) atomicOr(&g_flag_f32, 1);
}

// ---------------- fused kernel smem (floats) ----------------
// feat @0: 960 | score @960: 160 | wgt @1120: 160 | hbar @1280: 32*272=8704
// b2s @9984: 256 | fbs @10240: 256 | cidx @10496: 160 | anyv @10656: 32
// total 10688 floats = 42752 B  (3 CTAs/SM = 128 KB)
#define SMEM_BYTES 42752

__global__ void __launch_bounds__(256, 3) fused_all(
    const int* __restrict__ res_idx,
    const int* __restrict__ ss_idx,
    const float* __restrict__ dist,
    const int* __restrict__ seq_sep,
    const float* __restrict__ angles,
    const void* __restrict__ validp,
    const float* __restrict__ attn_W2,
    const float* __restrict__ attn_b2,
    const float* __restrict__ val_b2,
    const float* __restrict__ fallback,
    float* __restrict__ out)
{
    extern __shared__ float sm[];
    float* feat    = sm;
    float* score_s = sm + 960;
    float* wgt_s   = sm + 1120;
    float* hbar_s  = sm + 1280;
    float* b2s     = sm + 9984;
    float* fbs     = sm + 10240;
    int*   cidx    = (int*)(sm + 10496);
    int*   anyv_s  = (int*)(sm + 10656);

    const int tid  = threadIdx.x;
    const int lane = tid & 31;
    const int warp = tid >> 5;      // 0..7
    const int g    = lane >> 2;     // 0..7
    const int t    = lane & 3;      // 0..3
    const int b0   = blockIdx.x * TILE_B;
    const int gr0  = b0 * KNB;

    const float4* RS1a4 = (const float4*)g_RS1a;   // 32 f4 per row
    const float4* C1a4  = (const float4*)g_C1a;
    const float4* RS1v4 = (const float4*)g_RS1v;   // 64 f4 per row
    const float4* C1v4  = (const float4*)g_C1v;
    const uint32* hbU   = (const uint32*)hbar_s;
    const uint4*  w24   = (const uint4*)g_w2T;     // 64 uint4 per row

    // ---------- phase 0: constants + features + combined idx ----------
    if (tid < HID) { b2s[tid] = val_b2[tid]; fbs[tid] = fallback[tid]; }
    if (tid < ROWSF) {
        int gr = gr0 + tid;
        cidx[tid] = res_idx[gr] * NSS + ss_idx[gr];
        float d = dist[gr];
        if (d != d) d = 0.0f;
        feat[tid * 6 + 0] = d * (1.0f / 15.0f);
        feat[tid * 6 + 1] = log1pf(fabsf((float)seq_sep[gr])) * 0.2f;
        float4 a = ((const float4*)angles)[gr];
        feat[tid * 6 + 2] = (a.x != a.x) ? 0.0f : a.x;
        feat[tid * 6 + 3] = (a.y != a.y) ? 0.0f : a.y;
        feat[tid * 6 + 4] = (a.z != a.z) ? 0.0f : a.z;
        feat[tid * 6 + 5] = (a.w != a.w) ? 0.0f : a.w;
    }
    __syncthreads();

    // ---------- phase 1: attention scores (fused table, 1 ldg/row/lane) ----------
    // warp handles rows warp*20 .. warp*20+19 ; lane handles col quad = lane
    {
        float4 c1[6];
        #pragma unroll
        for (int j = 0; j < 6; j++) c1[j] = __ldg(C1a4 + j * 32 + lane);
        float4 w2q = __ldg(((const float4*)attn_W2) + lane);
        #pragma unroll 4
        for (int i = 0; i < 20; i++) {
            int j = warp * 20 + i;
            float4 p = __ldg(RS1a4 + cidx[j] * 32 + lane);
            const float* fj = feat + j * 6;
            #pragma unroll
            for (int jj = 0; jj < 6; jj++) {
                float f = fj[jj];
                p.x += f * c1[jj].x; p.y += f * c1[jj].y;
                p.z += f * c1[jj].z; p.w += f * c1[jj].w;
            }
            float part = gelu_fast(p.x) * w2q.x + gelu_fast(p.y) * w2q.y
                       + gelu_fast(p.z) * w2q.z + gelu_fast(p.w) * w2q.w;
            #pragma unroll
            for (int off = 16; off; off >>= 1)
                part += __shfl_xor_sync(0xFFFFFFFFu, part, off);
            if (lane == 0) score_s[j] = part;
        }
    }
    __syncthreads();

    // ---------- phase 2: softmax + validity (tid<32) ----------
    if (tid < TILE_B) {
        int gb = b0 + tid;
        float ab2 = attn_b2[0];
        int fu8 = g_flag_u8, ff32 = g_flag_f32;
        float s[KNB];
        int any = 0;
        #pragma unroll
        for (int k = 0; k < KNB; k++) {
            int idx = gb * KNB + k;
            int v;
            if (ff32)      v = (((const float*)validp)[idx] != 0.0f);
            else if (fu8)  v = (((const unsigned char*)validp)[idx] != 0);
            else           v = (((const int*)validp)[idx] != 0);
            any |= v;
            s[k] = v ? (score_s[tid * KNB + k] + ab2) : -10000.0f;
        }
        float m = s[0];
        #pragma unroll
        for (int k = 1; k < KNB; k++) m = fmaxf(m, s[k]);
        float e[KNB], sum = 0.0f;
        #pragma unroll
        for (int k = 0; k < KNB; k++) { e[k] = expf(s[k] - m); sum += e[k]; }
        float inv = 1.0f / sum;
        #pragma unroll
        for (int k = 0; k < KNB; k++) wgt_s[tid * KNB + k] = e[k] * inv;
        anyv_s[tid] = any;
    }
    __syncthreads();

    // ---------- phase 3: value path -> hbar (fused table, C1v hoisted) ----------
    // item = (b, q); q = tid&63 invariant; b = tid>>6 + 4*i
    {
        const int q = tid & 63;
        float4 c1[6];
        #pragma unroll
        for (int j = 0; j < 6; j++) c1[j] = __ldg(C1v4 + j * 64 + q);
        #pragma unroll 1
        for (int i = 0; i < 8; i++) {
            int b = (tid >> 6) + 4 * i;
            float ax = 0.0f, ay = 0.0f, az = 0.0f, aw = 0.0f;
            #pragma unroll
            for (int k = 0; k < KNB; k++) {
                int j = b * KNB + k;
                float wk = wgt_s[j];
                float4 p = __ldg(RS1v4 + cidx[j] * 64 + q);
                const float* fj = feat + j * 6;
                #pragma unroll
                for (int jj = 0; jj < 6; jj++) {
                    float f = fj[jj];
                    p.x += f * c1[jj].x; p.y += f * c1[jj].y;
                    p.z += f * c1[jj].z; p.w += f * c1[jj].w;
                }
                ax += wk * gelu_fast(p.x);
                ay += wk * gelu_fast(p.y);
                az += wk * gelu_fast(p.z);
                aw += wk * gelu_fast(p.w);
            }
            int col = q * 4;
            float* hb = hbar_s + b * HLD;
            hb[kperm16(col)]     = __uint_as_float(f2tf(ax));
            hb[kperm16(col + 1)] = __uint_as_float(f2tf(ay));
            hb[kperm16(col + 2)] = __uint_as_float(f2tf(az));
            hb[kperm16(col + 3)] = __uint_as_float(f2tf(aw));
        }
    }
    __syncthreads();

    // ---------- phase 4: output GEMM (32 x 256) @ (256 x 256), tensor cores ----------
    {
        const int nb2 = warp * 32;
        float acc[2][4][4];
        #pragma unroll
        for (int mi = 0; mi < 2; mi++)
            #pragma unroll
            for (int ni = 0; ni < 4; ni++)
                #pragma unroll
                for (int q = 0; q < 4; q++) acc[mi][ni][q] = 0.0f;

        #pragma unroll 2
        for (int ks = 0; ks < 16; ks++) {
            int kb = ks * 16;
            uint4 a0[2], a1[2];
            #pragma unroll
            for (int mi = 0; mi < 2; mi++) {
                const uint32* abase = hbU + (mi * 16 + g) * HLD + kb + 4 * t;
                a0[mi] = *(const uint4*)abase;
                a1[mi] = *(const uint4*)(abase + 8 * HLD);
            }
            #pragma unroll
            for (int ni = 0; ni < 4; ni++) {
                uint4 pb = __ldg(w24 + (nb2 + ni * 8 + g) * 64 + ks * 4 + t);
                #pragma unroll
                for (int mi = 0; mi < 2; mi++) {
                    mma_tf32(acc[mi][ni], a0[mi].x, a1[mi].x, a0[mi].y, a1[mi].y, pb.x, pb.y);
                    mma_tf32(acc[mi][ni], a0[mi].z, a1[mi].z, a0[mi].w, a1[mi].w, pb.z, pb.w);
                }
            }
        }

        #pragma unroll
        for (int mi = 0; mi < 2; mi++) {
            #pragma unroll
            for (int rh = 0; rh < 2; rh++) {
                int b = mi * 16 + g + 8 * rh;
                int av = anyv_s[b];
                int row = b0 + b;
                #pragma unroll
                for (int ni = 0; ni < 4; ni++) {
                    int colb = nb2 + ni * 8 + 2 * t;
                    float x0 = acc[mi][ni][rh * 2 + 0];
                    float x1 = acc[mi][ni][rh * 2 + 1];
                    float2 o;
                    if (av) { o.x = x0 + b2s[colb]; o.y = x1 + b2s[colb + 1]; }
                    else    { o.x = fbs[colb];      o.y = fbs[colb + 1]; }
                    *(float2*)(out + (size_t)row * HID + colb) = o;
                }
            }
        }
    }
}

// ---------------- launch ----------------
extern "C" void kernel_launch(void* const* d_in, const int* in_sizes, int n_in,
                              void* d_out, int out_size)
{
    const int*   res_idx   = (const int*)d_in[0];
    const int*   ss_idx    = (const int*)d_in[1];
    const float* dist      = (const float*)d_in[2];
    const int*   seq_sep   = (const int*)d_in[3];
    const float* angles    = (const float*)d_in[4];
    const void*  validp    = d_in[5];
    const float* res_table = (const float*)d_in[6];
    const float* ss_table  = (const float*)d_in[7];
    const float* cont_W    = (const float*)d_in[8];
    const float* cont_b    = (const float*)d_in[9];
    const float* attn_W1   = (const float*)d_in[10];
    const float* attn_b1   = (const float*)d_in[11];
    const float* attn_W2   = (const float*)d_in[12];
    const float* attn_b2   = (const float*)d_in[13];
    const float* val_W1    = (const float*)d_in[14];
    const float* val_b1    = (const float*)d_in[15];
    const float* val_W2    = (const float*)d_in[16];
    const float* val_b2    = (const float*)d_in[17];
    const float* fallback  = (const float*)d_in[18];
    float* out = (float*)d_out;

    reset_flags<<<1, 1>>>();
    detect_valid<<<148, 1024>>>((const unsigned int*)validp, (B_TOTAL * KNB) / 4);
    prep_tables<<<148, 256>>>(attn_W1, attn_b1, val_W1, val_b1, val_W2,
                              res_table, ss_table, cont_W, cont_b);
    prep_fuse<<<148, 256>>>();

    fused_all<<<B_TOTAL / TILE_B, 256, SMEM_BYTES>>>(
        res_idx, ss_idx, dist, seq_sep, angles, validp,
        attn_W2, attn_b2, val_b2, fallback, out);
}